// round 6
// baseline (speedup 1.0000x reference)
#include <cuda_runtime.h>
#include <math.h>
#include <stdint.h>

// Problem dims (fixed by reference)
#define N_B 64      // batch
#define T_S 128     // timesteps
#define V_S 20000   // vocab
#define E_S 16      // embed dim
#define H_S 256     // hidden
#define G_S 1024    // 4*H gates
#define NT  (N_B * T_S)          // 8192 rows
#define NTV ((long long)NT * V_S)

// ---------------- device scratch (no cudaMalloc allowed) ----------------
__device__ float g_g1pre[(size_t)T_S * G_S * N_B];   // [t][j][n]   32 MB
__device__ float g_h1a[H_S * N_B], g_h1b[H_S * N_B]; // states transposed [k][n]
__device__ float g_h2a[H_S * N_B], g_h2b[H_S * N_B];
__device__ float g_h3a[H_S * N_B], g_h3b[H_S * N_B];
__device__ float g_c1[H_S * N_B], g_c2[H_S * N_B], g_c3[H_S * N_B];
__device__ float g_bsum2[G_S], g_bsum3[G_S];
__device__ float g_h3all[(size_t)T_S * N_B * H_S];   // [t][n][k]    8 MB
__device__ float g_R[(size_t)NT * H_S];              // [row][k] row=n*T+t, 8 MB
__device__ float g_W1t[H_S * H_S];                   // [k][j]
__device__ float g_W2t[(size_t)H_S * V_S];           // [k][j]      20.5 MB

// ---------------- helpers ----------------
__device__ __forceinline__ float sigf(float x) { return 1.0f / (1.0f + expf(-x)); }

// packed fp32x2 FMA (Blackwell FFMA2; only reachable via PTX fma.rn.f32x2)
__device__ __forceinline__ void ffma2(unsigned long long& d, unsigned long long a,
                                      unsigned long long b) {
    asm("fma.rn.f32x2 %0, %1, %2, %0;" : "+l"(d) : "l"(a), "l"(b));
}
__device__ __forceinline__ unsigned long long pk2dup(float x) {
    unsigned long long r;
    asm("mov.b64 %0, {%1, %1};" : "=l"(r) : "f"(x));
    return r;
}
__device__ __forceinline__ float2 ull2f2(unsigned long long v) {
    float2 f;
    asm("mov.b64 {%0, %1}, %2;" : "=f"(f.x), "=f"(f.y) : "l"(v));
    return f;
}

// ---------------- prep kernels ----------------
__global__ void k_init_state(const float* __restrict__ h0, const float* __restrict__ c0) {
    int i = blockIdx.x * 256 + threadIdx.x;   // grid 64
    if (i >= H_S * N_B) return;
    int k = i / N_B, n = i % N_B;
    float h = h0[n * H_S + k];
    float c = c0[n * H_S + k];
    g_h1a[i] = h; g_h2a[i] = h; g_h3a[i] = h;
    g_c1[i] = c;  g_c2[i] = c;  g_c3[i] = c;
}

__global__ void k_bsum(const float* __restrict__ bih2, const float* __restrict__ bhh2,
                       const float* __restrict__ bih3, const float* __restrict__ bhh3) {
    int i = blockIdx.x * 256 + threadIdx.x;   // grid 8
    if (i < G_S)            g_bsum2[i] = bih2[i] + bhh2[i];
    else if (i < 2 * G_S)   g_bsum3[i - G_S] = bih3[i - G_S] + bhh3[i - G_S];
}

// tiled transpose: in[rows][cols] -> out[cols][rows]; which: 0 = W1t, 1 = W2t
__global__ void k_transpose(const float* __restrict__ in, int rows, int cols, int which) {
    float* out = which ? g_W2t : g_W1t;
    __shared__ float tile[32][33];
    int c0 = blockIdx.x * 32, r0 = blockIdx.y * 32;
    int tx = threadIdx.x, ty = threadIdx.y;   // 32 x 8
#pragma unroll
    for (int i = 0; i < 32; i += 8) {
        int r = r0 + ty + i, c = c0 + tx;
        if (r < rows && c < cols) tile[ty + i][tx] = in[(size_t)r * cols + c];
    }
    __syncthreads();
#pragma unroll
    for (int i = 0; i < 32; i += 8) {
        int c = c0 + ty + i, r = r0 + tx;
        if (r < rows && c < cols) out[(size_t)c * rows + r] = tile[tx][ty + i];
    }
}

// g1pre[t][j][n] = bih1[j] + bhh1[j] + sum_e emb[x[n,t],e] * Wih1[j,e]
__global__ __launch_bounds__(256) void k_embed(const int* __restrict__ x,
                                               const float* __restrict__ emb,
                                               const float* __restrict__ Wih1,
                                               const float* __restrict__ bih1,
                                               const float* __restrict__ bhh1) {
    __shared__ float es[N_B][E_S + 1];   // +1 pad -> conflict-free (17 coprime 32)
    __shared__ int xs[N_B];
    const int t = blockIdx.y;
    const int tid = threadIdx.x;
    if (tid < N_B) xs[tid] = x[tid * T_S + t];
    __syncthreads();
    for (int i = tid; i < N_B * E_S; i += 256) {
        int nn = i >> 4, e = i & 15;
        es[nn][e] = emb[(size_t)xs[nn] * E_S + e];
    }
    __syncthreads();
    const int n = tid & 63;
    const int j = blockIdx.x * 4 + (tid >> 6);
    float acc = bih1[j] + bhh1[j];
    const float* w = Wih1 + j * E_S;
#pragma unroll
    for (int e = 0; e < E_S; e++) acc = fmaf(es[n][e], w[e], acc);
    g_g1pre[((size_t)t * G_S + j) * N_B + n] = acc;
}

// ---------------- LSTM cell kernels ----------------
// thread = (n, jh); warp = 32 consecutive n of one jh -> coalesced act loads,
// warp-uniform weight loads (LDG.128). grid 64 x 256 threads.
__global__ __launch_bounds__(256) void k_cell1(int t, const float* __restrict__ Whh) {
    const int n  = threadIdx.x & 63;
    const int jh = (blockIdx.x << 2) + (threadIdx.x >> 6);
    const float* pre  = g_g1pre + (size_t)t * (G_S * N_B);
    const float* hin  = (t & 1) ? g_h1b : g_h1a;
    float*       hout = (t & 1) ? g_h1a : g_h1b;

    float ai = pre[(jh        ) * N_B + n];
    float af = pre[(jh + H_S  ) * N_B + n];
    float ag = pre[(jh + 2*H_S) * N_B + n];
    float ao = pre[(jh + 3*H_S) * N_B + n];

    const float4* wi = (const float4*)(Whh + (size_t)(jh        ) * H_S);
    const float4* wf = (const float4*)(Whh + (size_t)(jh + H_S  ) * H_S);
    const float4* wg = (const float4*)(Whh + (size_t)(jh + 2*H_S) * H_S);
    const float4* wo = (const float4*)(Whh + (size_t)(jh + 3*H_S) * H_S);
#pragma unroll 2
    for (int k4 = 0; k4 < H_S / 4; ++k4) {
        float4 vi = wi[k4], vf = wf[k4], vg = wg[k4], vo = wo[k4];
        const float* hp = hin + k4 * (4 * N_B) + n;
        float a0 = hp[0], a1 = hp[N_B], a2 = hp[2 * N_B], a3 = hp[3 * N_B];
        ai = fmaf(a0, vi.x, ai); ai = fmaf(a1, vi.y, ai); ai = fmaf(a2, vi.z, ai); ai = fmaf(a3, vi.w, ai);
        af = fmaf(a0, vf.x, af); af = fmaf(a1, vf.y, af); af = fmaf(a2, vf.z, af); af = fmaf(a3, vf.w, af);
        ag = fmaf(a0, vg.x, ag); ag = fmaf(a1, vg.y, ag); ag = fmaf(a2, vg.z, ag); ag = fmaf(a3, vg.w, ag);
        ao = fmaf(a0, vo.x, ao); ao = fmaf(a1, vo.y, ao); ao = fmaf(a2, vo.z, ao); ao = fmaf(a3, vo.w, ao);
    }
    const int si = jh * N_B + n;
    float cprev = g_c1[si];
    float cn = sigf(af) * cprev + sigf(ai) * tanhf(ag);
    g_c1[si] = cn;
    hout[si] = sigf(ao) * tanhf(cn);
}

template <int L>
__global__ __launch_bounds__(256) void k_cell23(int t, const float* __restrict__ Wih,
                                                const float* __restrict__ Whh) {
    const int n  = threadIdx.x & 63;
    const int jh = (blockIdx.x << 2) + (threadIdx.x >> 6);

    const float *xin, *hin, *bsum;
    float *hout, *cst;
    if (L == 2) {
        xin  = (t & 1) ? g_h1a : g_h1b;   // layer-1 output at step t
        hin  = (t & 1) ? g_h2b : g_h2a;
        hout = (t & 1) ? g_h2a : g_h2b;
        cst  = g_c2; bsum = g_bsum2;
    } else {
        xin  = (t & 1) ? g_h2a : g_h2b;   // layer-2 output at step t
        hin  = (t & 1) ? g_h3b : g_h3a;
        hout = (t & 1) ? g_h3a : g_h3b;
        cst  = g_c3; bsum = g_bsum3;
    }

    float ai = bsum[jh];
    float af = bsum[jh + H_S];
    float ag = bsum[jh + 2 * H_S];
    float ao = bsum[jh + 3 * H_S];

    // input-to-hidden part
    {
        const float4* wi = (const float4*)(Wih + (size_t)(jh        ) * H_S);
        const float4* wf = (const float4*)(Wih + (size_t)(jh + H_S  ) * H_S);
        const float4* wg = (const float4*)(Wih + (size_t)(jh + 2*H_S) * H_S);
        const float4* wo = (const float4*)(Wih + (size_t)(jh + 3*H_S) * H_S);
#pragma unroll 2
        for (int k4 = 0; k4 < H_S / 4; ++k4) {
            float4 vi = wi[k4], vf = wf[k4], vg = wg[k4], vo = wo[k4];
            const float* xp = xin + k4 * (4 * N_B) + n;
            float a0 = xp[0], a1 = xp[N_B], a2 = xp[2 * N_B], a3 = xp[3 * N_B];
            ai = fmaf(a0, vi.x, ai); ai = fmaf(a1, vi.y, ai); ai = fmaf(a2, vi.z, ai); ai = fmaf(a3, vi.w, ai);
            af = fmaf(a0, vf.x, af); af = fmaf(a1, vf.y, af); af = fmaf(a2, vf.z, af); af = fmaf(a3, vf.w, af);
            ag = fmaf(a0, vg.x, ag); ag = fmaf(a1, vg.y, ag); ag = fmaf(a2, vg.z, ag); ag = fmaf(a3, vg.w, ag);
            ao = fmaf(a0, vo.x, ao); ao = fmaf(a1, vo.y, ao); ao = fmaf(a2, vo.z, ao); ao = fmaf(a3, vo.w, ao);
        }
    }
    // hidden-to-hidden part
    {
        const float4* wi = (const float4*)(Whh + (size_t)(jh        ) * H_S);
        const float4* wf = (const float4*)(Whh + (size_t)(jh + H_S  ) * H_S);
        const float4* wg = (const float4*)(Whh + (size_t)(jh + 2*H_S) * H_S);
        const float4* wo = (const float4*)(Whh + (size_t)(jh + 3*H_S) * H_S);
#pragma unroll 2
        for (int k4 = 0; k4 < H_S / 4; ++k4) {
            float4 vi = wi[k4], vf = wf[k4], vg = wg[k4], vo = wo[k4];
            const float* hp = hin + k4 * (4 * N_B) + n;
            float a0 = hp[0], a1 = hp[N_B], a2 = hp[2 * N_B], a3 = hp[3 * N_B];
            ai = fmaf(a0, vi.x, ai); ai = fmaf(a1, vi.y, ai); ai = fmaf(a2, vi.z, ai); ai = fmaf(a3, vi.w, ai);
            af = fmaf(a0, vf.x, af); af = fmaf(a1, vf.y, af); af = fmaf(a2, vf.z, af); af = fmaf(a3, vf.w, af);
            ag = fmaf(a0, vg.x, ag); ag = fmaf(a1, vg.y, ag); ag = fmaf(a2, vg.z, ag); ag = fmaf(a3, vg.w, ag);
            ao = fmaf(a0, vo.x, ao); ao = fmaf(a1, vo.y, ao); ao = fmaf(a2, vo.z, ao); ao = fmaf(a3, vo.w, ao);
        }
    }
    const int si = jh * N_B + n;
    float cprev = cst[si];
    float cn = sigf(af) * cprev + sigf(ai) * tanhf(ag);
    cst[si] = cn;
    float hn = sigf(ao) * tanhf(cn);
    hout[si] = hn;
    if (L == 3) g_h3all[((size_t)t * N_B + n) * H_S + jh] = hn;  // [t][n][k]
}

// ---------------- MLP layer 1 (+ReLU): R[row][j] = relu(h3[row] @ W1^T + b1) ----------
__global__ __launch_bounds__(256) void k_mlp1(const float* __restrict__ b1) {
    __shared__ float hs[16][H_S];
    const int tid = threadIdx.x;             // = output column j
    const int r0 = blockIdx.x * 16;          // 512 blocks
#pragma unroll
    for (int it = 0; it < 16; ++it) {
        int row = r0 + it;                   // row = n*T + t
        int n = row >> 7, t = row & (T_S - 1);
        hs[it][tid] = g_h3all[((size_t)t * N_B + n) * H_S + tid];
    }
    __syncthreads();
    float acc[16];
#pragma unroll
    for (int r = 0; r < 16; ++r) acc[r] = 0.0f;
#pragma unroll 4
    for (int k = 0; k < H_S; ++k) {
        float w = g_W1t[k * H_S + tid];
#pragma unroll
        for (int r = 0; r < 16; ++r) acc[r] = fmaf(hs[r][k], w, acc[r]);
    }
    float bb = b1[tid];
#pragma unroll
    for (int r = 0; r < 16; ++r) {
        float v = acc[r] + bb;
        g_R[(size_t)(r0 + r) * H_S + tid] = v > 0.0f ? v : 0.0f;
    }
}

// ---------------- vocab projection: C[8192,20000] = R @ W2t + b2 ----------------
#define BM 128
#define BN 128
#define BK 16
__global__ __launch_bounds__(256, 2) void k_out(const float* __restrict__ b2,
                                                float* __restrict__ C) {
    __shared__ float As[BK][BM];   // [k][m]
    __shared__ float Bs[BK][BN];   // [k][n]
    const int tid = threadIdx.x;
    const int bn = blockIdx.x * BN;
    const int bm = blockIdx.y * BM;
    const int tx = tid & 15, ty = tid >> 4;
    const int m0 = ty * 8, n0 = tx * 8;

    unsigned long long acc[8][4];
#pragma unroll
    for (int i = 0; i < 8; ++i)
#pragma unroll
        for (int j = 0; j < 4; ++j) acc[i][j] = 0ull;

    for (int k0 = 0; k0 < H_S; k0 += BK) {
        // A tile: 128 rows x 16 k, stored transposed [k][m]
#pragma unroll
        for (int s = tid; s < (BM * BK) / 4; s += 256) {
            int row = s >> 2, kq = (s & 3) << 2;
            float4 v = *(const float4*)(g_R + (size_t)(bm + row) * H_S + k0 + kq);
            As[kq + 0][row] = v.x; As[kq + 1][row] = v.y;
            As[kq + 2][row] = v.z; As[kq + 3][row] = v.w;
        }
        // B tile: 16 k x 128 cols
#pragma unroll
        for (int s = tid; s < (BK * BN) / 4; s += 256) {
            int kr = s >> 5, cq = (s & 31) << 2;
            int col = bn + cq;
            float4 v = make_float4(0.f, 0.f, 0.f, 0.f);
            if (col < V_S) v = *(const float4*)(g_W2t + (size_t)(k0 + kr) * V_S + col);
            *(float4*)&Bs[kr][cq] = v;
        }
        __syncthreads();
#pragma unroll
        for (int k = 0; k < BK; ++k) {
            float4 a0 = *(const float4*)&As[k][m0];
            float4 a1 = *(const float4*)&As[k][m0 + 4];
            ulonglong2 bb0 = *(const ulonglong2*)&Bs[k][n0];
            ulonglong2 bb1 = *(const ulonglong2*)&Bs[k][n0 + 4];
            unsigned long long br[4] = { bb0.x, bb0.y, bb1.x, bb1.y };
            float ar[8] = { a0.x, a0.y, a0.z, a0.w, a1.x, a1.y, a1.z, a1.w };
#pragma unroll
            for (int i = 0; i < 8; ++i) {
                unsigned long long ad = pk2dup(ar[i]);
#pragma unroll
                for (int j = 0; j < 4; ++j) ffma2(acc[i][j], ad, br[j]);
            }
        }
        __syncthreads();
    }
    // epilogue: + b2, guarded float4 stores (V_S % 4 == 0)
#pragma unroll
    for (int i = 0; i < 8; ++i) {
        size_t rowoff = (size_t)(bm + m0 + i) * V_S;
#pragma unroll
        for (int jq = 0; jq < 2; ++jq) {
            int col = bn + n0 + jq * 4;
            if (col < V_S) {
                float4 bias = *(const float4*)(b2 + col);
                float2 p0 = ull2f2(acc[i][jq * 2]);
                float2 p1 = ull2f2(acc[i][jq * 2 + 1]);
                float4 o = make_float4(p0.x + bias.x, p0.y + bias.y,
                                       p1.x + bias.z, p1.y + bias.w);
                *(float4*)(C + rowoff + col) = o;
            }
        }
    }
}

// labels (second reference output, cast to output dtype)
__global__ void k_labels(const int* __restrict__ x, float* __restrict__ out, long long out_size) {
    int i = blockIdx.x * 256 + threadIdx.x;
    if (i < NT && NTV + i < out_size) out[NTV + i] = (float)x[i];
}

// ---------------- host launcher ----------------
extern "C" void kernel_launch(void* const* d_in, const int* in_sizes, int n_in,
                              void* d_out, int out_size) {
    const int*   x    = (const int*)d_in[0];
    const float* h0   = (const float*)d_in[1];
    const float* c0   = (const float*)d_in[2];
    const float* emb  = (const float*)d_in[3];
    const float* Wih1 = (const float*)d_in[4];
    const float* Whh1 = (const float*)d_in[5];
    const float* bih1 = (const float*)d_in[6];
    const float* bhh1 = (const float*)d_in[7];
    const float* Wih2 = (const float*)d_in[8];
    const float* Whh2 = (const float*)d_in[9];
    const float* bih2 = (const float*)d_in[10];
    const float* bhh2 = (const float*)d_in[11];
    const float* Wih3 = (const float*)d_in[12];
    const float* Whh3 = (const float*)d_in[13];
    const float* bih3 = (const float*)d_in[14];
    const float* bhh3 = (const float*)d_in[15];
    const float* W1   = (const float*)d_in[16];
    const float* b1   = (const float*)d_in[17];
    const float* W2   = (const float*)d_in[18];
    const float* b2   = (const float*)d_in[19];
    float* out = (float*)d_out;

    // prep
    k_init_state<<<64, 256>>>(h0, c0);
    k_bsum<<<8, 256>>>(bih2, bhh2, bih3, bhh3);
    k_transpose<<<dim3(8, 8), dim3(32, 8)>>>(W1, H_S, H_S, 0);                 // W1t
    k_transpose<<<dim3(8, (V_S + 31) / 32), dim3(32, 8)>>>(W2, V_S, H_S, 1);   // W2t
    k_embed<<<dim3(G_S / 4, T_S), 256>>>(x, emb, Wih1, bih1, bhh1);

    // sequential recurrence: 3 cell kernels per timestep
    for (int t = 0; t < T_S; ++t) {
        k_cell1<<<64, 256>>>(t, Whh1);
        k_cell23<2><<<64, 256>>>(t, Wih2, Whh2);
        k_cell23<3><<<64, 256>>>(t, Wih3, Whh3);
    }

    // batched head
    k_mlp1<<<NT / 16, 256>>>(b1);
    k_out<<<dim3((V_S + BN - 1) / BN, NT / BM), 256>>>(b2, out);

    if ((long long)out_size > NTV)
        k_labels<<<(NT + 255) / 256, 256>>>(x, out, (long long)out_size);
}

// round 8
// speedup vs baseline: 2.5167x; 2.5167x over previous
#include <cuda_runtime.h>
#include <math.h>
#include <stdint.h>

// Problem dims (fixed by reference)
#define N_B 64      // batch
#define T_S 128     // timesteps
#define V_S 20000   // vocab
#define E_S 16      // embed dim
#define H_S 256     // hidden
#define G_S 1024    // 4*H gates
#define NT  (N_B * T_S)          // 8192 rows
#define NTV ((long long)NT * V_S)

#define RNN_BLOCKS 64
#define RNN_THREADS 128

// ---------------- device scratch (no cudaMalloc allowed) ----------------
__device__ float g_g1pre[(size_t)T_S * G_S * N_B];     // [t][j][n]   32 MB
__device__ float g_h1a[H_S * N_B], g_h1b[H_S * N_B];   // states [k][n]
__device__ float g_h2a[H_S * N_B], g_h2b[H_S * N_B];
__device__ float g_h3seq[(size_t)(T_S + 1) * H_S * N_B]; // slot s = h3 after step s-1, [k][n]
__device__ float g_R[(size_t)NT * H_S];                // [row][k] row=n*T+t
__device__ float g_W1t[H_S * H_S];                     // [k][j]
__device__ float g_W2t[(size_t)H_S * V_S];             // [k][j]   20.5 MB
__device__ unsigned g_bar[2 * T_S + 1];                // grid-barrier counters (zero-init; block 0 resets at end)

// ---------------- helpers ----------------
__device__ __forceinline__ float sigf(float x) { return __fdividef(1.0f, 1.0f + __expf(-x)); }

// packed fp32x2 FMA (Blackwell FFMA2; only reachable via PTX fma.rn.f32x2)
__device__ __forceinline__ void ffma2(unsigned long long& d, unsigned long long a,
                                      unsigned long long b) {
    asm("fma.rn.f32x2 %0, %1, %2, %0;" : "+l"(d) : "l"(a), "l"(b));
}
__device__ __forceinline__ unsigned long long pk2dup(float x) {
    unsigned long long r;
    asm("mov.b64 %0, {%1, %1};" : "=l"(r) : "f"(x));
    return r;
}
__device__ __forceinline__ float2 u2f(unsigned long long v) {
    float2 f;
    asm("mov.b64 {%0, %1}, %2;" : "=f"(f.x), "=f"(f.y) : "l"(v));
    return f;
}
__device__ __forceinline__ unsigned long long f2u(float x, float y) {
    unsigned long long v;
    asm("mov.b64 %0, {%1, %2};" : "=l"(v) : "f"(x), "f"(y));
    return v;
}
// 8-byte activation load bypassing L1 (cross-block-produced data)
__device__ __forceinline__ unsigned long long lda_cg(const float* p) {
    unsigned long long v;
    asm volatile("ld.global.cg.b64 %0, [%1];" : "=l"(v) : "l"(p));
    return v;
}
__device__ __forceinline__ void sta_cg(float* p, float x, float y) {
    asm volatile("st.global.cg.v2.f32 [%0], {%1, %2};" :: "l"(p), "f"(x), "f"(y) : "memory");
}

// software grid barrier across the 64 co-resident blocks.
// Release: fence + arrive. Acquire: spin until count==RNN_BLOCKS, fence, bar.
// Each counter is used exactly once per run, so no reset race exists for the
// per-step barriers; the FINAL barrier uses an arrive-only protocol (see k_rnn).
__device__ __forceinline__ void gbar(unsigned idx) {
    __threadfence();
    __syncthreads();
    if (threadIdx.x == 0) {
        atomicAdd(&g_bar[idx], 1u);
        while (((volatile unsigned*)g_bar)[idx] < (unsigned)RNN_BLOCKS) { }
        __threadfence();   // acquire side
    }
    __syncthreads();
}

// ---------------- prep kernels ----------------
__global__ void k_init_state(const float* __restrict__ h0) {
    int i = blockIdx.x * 256 + threadIdx.x;   // grid 64
    if (i >= H_S * N_B) return;
    int k = i / N_B, n = i % N_B;
    float h = h0[n * H_S + k];
    g_h1a[i] = h; g_h2a[i] = h; g_h3seq[i] = h;   // h3seq slot 0
}

// tiled transpose: in[rows][cols] -> out[cols][rows]; which: 0 = W1t, 1 = W2t
__global__ void k_transpose(const float* __restrict__ in, int rows, int cols, int which) {
    float* out = which ? g_W2t : g_W1t;
    __shared__ float tile[32][33];
    int c0 = blockIdx.x * 32, r0 = blockIdx.y * 32;
    int tx = threadIdx.x, ty = threadIdx.y;   // 32 x 8
#pragma unroll
    for (int i = 0; i < 32; i += 8) {
        int r = r0 + ty + i, c = c0 + tx;
        if (r < rows && c < cols) tile[ty + i][tx] = in[(size_t)r * cols + c];
    }
    __syncthreads();
#pragma unroll
    for (int i = 0; i < 32; i += 8) {
        int c = c0 + ty + i, r = r0 + tx;
        if (r < rows && c < cols) out[(size_t)c * rows + r] = tile[tx][ty + i];
    }
}

// g1pre[t][j][n] = bih1[j] + bhh1[j] + sum_e emb[x[n,t],e] * Wih1[j,e]
__global__ __launch_bounds__(256) void k_embed(const int* __restrict__ x,
                                               const float* __restrict__ emb,
                                               const float* __restrict__ Wih1,
                                               const float* __restrict__ bih1,
                                               const float* __restrict__ bhh1) {
    __shared__ float es[N_B][E_S + 1];
    __shared__ int xs[N_B];
    const int t = blockIdx.y;
    const int tid = threadIdx.x;
    if (tid < N_B) xs[tid] = x[tid * T_S + t];
    __syncthreads();
    for (int i = tid; i < N_B * E_S; i += 256) {
        int nn = i >> 4, e = i & 15;
        es[nn][e] = emb[(size_t)xs[nn] * E_S + e];
    }
    __syncthreads();
    const int n = tid & 63;
    const int j = blockIdx.x * 4 + (tid >> 6);
    float acc = bih1[j] + bhh1[j];
    const float* w = Wih1 + j * E_S;
#pragma unroll
    for (int e = 0; e < E_S; e++) acc = fmaf(es[n][e], w[e], acc);
    g_g1pre[((size_t)t * G_S + j) * N_B + n] = acc;
}

// ---------------- persistent fused 3-layer LSTM kernel ----------------
// 64 blocks x 128 threads. Warp w handles gate-row jh = 4*block + w; lane l
// handles the n-pair (2l, 2l+1). Weights (f32x2-duplicated) live in 160KB
// dynamic SMEM for the whole run; c-states live in registers; h-states go
// through L2 (.cg) with software grid barriers.
//
// Barrier schedule per step t:  L1 -> gbar(2t) -> L2 -> gbar(2t+1) -> L3.
// No barrier after L3: L1(t+1) doesn't read h3, and any block's L3(t+1)
// happens after it passed gbar(2t+3), whose arrivals all happen after every
// block finished L3(t). WAR on ping-pong h1/h2 buffers is covered by the
// same chain (readers of a parity buffer are >=2 barriers behind rewriters).

__device__ __forceinline__ void mat_acc(const float* __restrict__ acts,
                                        const unsigned long long* __restrict__ wd,
                                        int n2, unsigned long long acc[4]) {
#pragma unroll 4
    for (int k4 = 0; k4 < H_S / 4; ++k4) {
        const float* ap = acts + (k4 * 4) * N_B + n2;
        unsigned long long a0 = lda_cg(ap);
        unsigned long long a1 = lda_cg(ap + N_B);
        unsigned long long a2 = lda_cg(ap + 2 * N_B);
        unsigned long long a3 = lda_cg(ap + 3 * N_B);
#pragma unroll
        for (int g = 0; g < 4; ++g) {
            const ulonglong2* w2 = (const ulonglong2*)(wd + g * H_S + k4 * 4);
            ulonglong2 w01 = w2[0];
            ulonglong2 w23 = w2[1];
            ffma2(acc[g], w01.x, a0);
            ffma2(acc[g], w01.y, a1);
            ffma2(acc[g], w23.x, a2);
            ffma2(acc[g], w23.y, a3);
        }
    }
}

__device__ __forceinline__ void cellfin(const unsigned long long acc[4],
                                        unsigned long long& cpk,
                                        float* __restrict__ hout, int jh, int n2) {
    float2 ai = u2f(acc[0]), af = u2f(acc[1]), ag = u2f(acc[2]), ao = u2f(acc[3]);
    float2 c = u2f(cpk);
    float c0n = sigf(af.x) * c.x + sigf(ai.x) * tanhf(ag.x);
    float c1n = sigf(af.y) * c.y + sigf(ai.y) * tanhf(ag.y);
    float h0 = sigf(ao.x) * tanhf(c0n);
    float h1 = sigf(ao.y) * tanhf(c1n);
    cpk = f2u(c0n, c1n);
    sta_cg(hout + jh * N_B + n2, h0, h1);
}

__global__ __launch_bounds__(RNN_THREADS, 1) void k_rnn(
    const float* __restrict__ Whh1,
    const float* __restrict__ Wih2, const float* __restrict__ Whh2,
    const float* __restrict__ Wih3, const float* __restrict__ Whh3,
    const float* __restrict__ bih2, const float* __restrict__ bhh2,
    const float* __restrict__ bih3, const float* __restrict__ bhh3,
    const float* __restrict__ c0) {
    extern __shared__ unsigned long long wsd[];   // [5][4 warps][4 gates][256 k] dup pairs
    const int tid  = threadIdx.x;
    const int w    = tid >> 5;
    const int lane = tid & 31;
    const int n2   = lane * 2;
    const int jh   = blockIdx.x * 4 + w;

    // one-time weight preload, duplicated for f32x2 (coalesced LDG, linear STS)
    const float* Wsrc[5] = { Whh1, Wih2, Whh2, Wih3, Whh3 };
    for (int idx = tid; idx < 5 * 4 * 4 * H_S; idx += RNN_THREADS) {
        int mat  = idx >> 12;
        int ww   = (idx >> 10) & 3;
        int gate = (idx >> 8) & 3;
        int k    = idx & 255;
        float v = __ldg(Wsrc[mat] + (size_t)(gate * H_S + blockIdx.x * 4 + ww) * H_S + k);
        wsd[idx] = pk2dup(v);
    }
    // bias sums (packed, duplicated) and register-resident c states
    unsigned long long b2[4], b3[4];
#pragma unroll
    for (int g = 0; g < 4; ++g) {
        b2[g] = pk2dup(bih2[g * H_S + jh] + bhh2[g * H_S + jh]);
        b3[g] = pk2dup(bih3[g * H_S + jh] + bhh3[g * H_S + jh]);
    }
    unsigned long long c1 = f2u(c0[n2 * H_S + jh], c0[(n2 + 1) * H_S + jh]);
    unsigned long long c2 = c1, c3 = c1;
    __syncthreads();

    const unsigned long long* wd1  = wsd + ((0 * 4 + w) * 4) * H_S;
    const unsigned long long* wdi2 = wsd + ((1 * 4 + w) * 4) * H_S;
    const unsigned long long* wdh2 = wsd + ((2 * 4 + w) * 4) * H_S;
    const unsigned long long* wdi3 = wsd + ((3 * 4 + w) * 4) * H_S;
    const unsigned long long* wdh3 = wsd + ((4 * 4 + w) * 4) * H_S;

    for (int t = 0; t < T_S; ++t) {
        const float* h1in  = (t & 1) ? g_h1b : g_h1a;
        float*       h1out = (t & 1) ? g_h1a : g_h1b;
        const float* h2in  = (t & 1) ? g_h2b : g_h2a;
        float*       h2out = (t & 1) ? g_h2a : g_h2b;
        const float* h3in  = g_h3seq + (size_t)t * (H_S * N_B);
        float*       h3out = g_h3seq + (size_t)(t + 1) * (H_S * N_B);

        // ---- layer 1 (input part precomputed in g_g1pre) ----
        {
            const float* pre = g_g1pre + (size_t)t * (G_S * N_B);
            unsigned long long acc[4];
#pragma unroll
            for (int g = 0; g < 4; ++g)
                acc[g] = *(const unsigned long long*)(pre + (size_t)(g * H_S + jh) * N_B + n2);
            mat_acc(h1in, wd1, n2, acc);
            cellfin(acc, c1, h1out, jh, n2);
        }
        gbar(2 * t);
        // ---- layer 2 ----
        {
            unsigned long long acc[4] = { b2[0], b2[1], b2[2], b2[3] };
            mat_acc(h1out, wdi2, n2, acc);
            mat_acc(h2in,  wdh2, n2, acc);
            cellfin(acc, c2, h2out, jh, n2);
        }
        gbar(2 * t + 1);
        // ---- layer 3 (no trailing barrier needed; see header comment) ----
        {
            unsigned long long acc[4] = { b3[0], b3[1], b3[2], b3[3] };
            mat_acc(h2out, wdi3, n2, acc);
            mat_acc(h3in,  wdh3, n2, acc);
            cellfin(acc, c3, h3out, jh, n2);
        }
    }

    // ---- final barrier: arrive-only for blocks 1..63; block 0 waits and
    // then single-handedly resets all counters. Exiting blocks never read
    // g_bar again, so the reset cannot race with a spinning waiter. ----
    __threadfence();
    __syncthreads();
    if (blockIdx.x != 0) {
        if (tid == 0) atomicAdd(&g_bar[2 * T_S], 1u);
        return;
    }
    if (tid == 0) {
        atomicAdd(&g_bar[2 * T_S], 1u);
        while (((volatile unsigned*)g_bar)[2 * T_S] < (unsigned)RNN_BLOCKS) { }
        __threadfence();
    }
    __syncthreads();
    for (int i = tid; i <= 2 * T_S; i += RNN_THREADS) g_bar[i] = 0;
}

// ---------------- MLP layer 1 (+ReLU), block per timestep ----------------
// R[n*T+t][j] = relu(sum_k h3seq[t+1][k][n] * W1t[k][j] + b1[j])
__global__ __launch_bounds__(256) void k_mlp1(const float* __restrict__ b1) {
    extern __shared__ float hs[];             // [256 k][64 n] = 64KB
    const int t = blockIdx.x;
    const int j = threadIdx.x;
    const float4* src = (const float4*)(g_h3seq + (size_t)(t + 1) * (H_S * N_B));
    float4* hs4 = (float4*)hs;
    for (int i = j; i < H_S * N_B / 4; i += 256) hs4[i] = src[i];
    __syncthreads();
    float bb = b1[j];
#pragma unroll 1
    for (int pass = 0; pass < 4; ++pass) {
        float acc[16];
#pragma unroll
        for (int i = 0; i < 16; ++i) acc[i] = 0.0f;
#pragma unroll 4
        for (int k = 0; k < H_S; ++k) {
            float wv = g_W1t[k * H_S + j];
            const float4* hp = (const float4*)(hs + k * N_B + pass * 16);
            float4 h0 = hp[0], h1 = hp[1], h2 = hp[2], h3 = hp[3];
            acc[0]  = fmaf(h0.x, wv, acc[0]);  acc[1]  = fmaf(h0.y, wv, acc[1]);
            acc[2]  = fmaf(h0.z, wv, acc[2]);  acc[3]  = fmaf(h0.w, wv, acc[3]);
            acc[4]  = fmaf(h1.x, wv, acc[4]);  acc[5]  = fmaf(h1.y, wv, acc[5]);
            acc[6]  = fmaf(h1.z, wv, acc[6]);  acc[7]  = fmaf(h1.w, wv, acc[7]);
            acc[8]  = fmaf(h2.x, wv, acc[8]);  acc[9]  = fmaf(h2.y, wv, acc[9]);
            acc[10] = fmaf(h2.z, wv, acc[10]); acc[11] = fmaf(h2.w, wv, acc[11]);
            acc[12] = fmaf(h3.x, wv, acc[12]); acc[13] = fmaf(h3.y, wv, acc[13]);
            acc[14] = fmaf(h3.z, wv, acc[14]); acc[15] = fmaf(h3.w, wv, acc[15]);
        }
#pragma unroll
        for (int i = 0; i < 16; ++i) {
            int n = pass * 16 + i;
            float v = acc[i] + bb;
            g_R[((size_t)n * T_S + t) * H_S + j] = v > 0.0f ? v : 0.0f;
        }
    }
}

// ---------------- vocab projection: C[8192,20000] = R @ W2t + b2 ----------------
#define BM 128
#define BN 128
#define BK 16
__global__ __launch_bounds__(256, 2) void k_out(const float* __restrict__ b2,
                                                float* __restrict__ C) {
    __shared__ float As[BK][BM];   // [k][m]
    __shared__ float Bs[BK][BN];   // [k][n]
    const int tid = threadIdx.x;
    const int bn = blockIdx.x * BN;
    const int bm = blockIdx.y * BM;
    const int tx = tid & 15, ty = tid >> 4;
    const int m0 = ty * 8, n0 = tx * 8;

    unsigned long long acc[8][4];
#pragma unroll
    for (int i = 0; i < 8; ++i)
#pragma unroll
        for (int j = 0; j < 4; ++j) acc[i][j] = 0ull;

    for (int k0 = 0; k0 < H_S; k0 += BK) {
#pragma unroll
        for (int s = tid; s < (BM * BK) / 4; s += 256) {
            int row = s >> 2, kq = (s & 3) << 2;
            float4 v = *(const float4*)(g_R + (size_t)(bm + row) * H_S + k0 + kq);
            As[kq + 0][row] = v.x; As[kq + 1][row] = v.y;
            As[kq + 2][row] = v.z; As[kq + 3][row] = v.w;
        }
#pragma unroll
        for (int s = tid; s < (BK * BN) / 4; s += 256) {
            int kr = s >> 5, cq = (s & 31) << 2;
            int col = bn + cq;
            float4 v = make_float4(0.f, 0.f, 0.f, 0.f);
            if (col < V_S) v = *(const float4*)(g_W2t + (size_t)(k0 + kr) * V_S + col);
            *(float4*)&Bs[kr][cq] = v;
        }
        __syncthreads();
#pragma unroll
        for (int k = 0; k < BK; ++k) {
            float4 a0 = *(const float4*)&As[k][m0];
            float4 a1 = *(const float4*)&As[k][m0 + 4];
            ulonglong2 bb0 = *(const ulonglong2*)&Bs[k][n0];
            ulonglong2 bb1 = *(const ulonglong2*)&Bs[k][n0 + 4];
            unsigned long long br[4] = { bb0.x, bb0.y, bb1.x, bb1.y };
            float ar[8] = { a0.x, a0.y, a0.z, a0.w, a1.x, a1.y, a1.z, a1.w };
#pragma unroll
            for (int i = 0; i < 8; ++i) {
                unsigned long long ad = pk2dup(ar[i]);
#pragma unroll
                for (int j = 0; j < 4; ++j) ffma2(acc[i][j], ad, br[j]);
            }
        }
        __syncthreads();
    }
#pragma unroll
    for (int i = 0; i < 8; ++i) {
        size_t rowoff = (size_t)(bm + m0 + i) * V_S;
#pragma unroll
        for (int jq = 0; jq < 2; ++jq) {
            int col = bn + n0 + jq * 4;
            if (col < V_S) {
                float4 bias = *(const float4*)(b2 + col);
                float2 p0 = u2f(acc[i][jq * 2]);
                float2 p1 = u2f(acc[i][jq * 2 + 1]);
                float4 o = make_float4(p0.x + bias.x, p0.y + bias.y,
                                       p1.x + bias.z, p1.y + bias.w);
                *(float4*)(C + rowoff + col) = o;
            }
        }
    }
}

// labels (second reference output, cast to output dtype)
__global__ void k_labels(const int* __restrict__ x, float* __restrict__ out, long long out_size) {
    int i = blockIdx.x * 256 + threadIdx.x;
    if (i < NT && NTV + i < out_size) out[NTV + i] = (float)x[i];
}

// ---------------- host launcher ----------------
extern "C" void kernel_launch(void* const* d_in, const int* in_sizes, int n_in,
                              void* d_out, int out_size) {
    const int*   x    = (const int*)d_in[0];
    const float* h0   = (const float*)d_in[1];
    const float* c0   = (const float*)d_in[2];
    const float* emb  = (const float*)d_in[3];
    const float* Wih1 = (const float*)d_in[4];
    const float* Whh1 = (const float*)d_in[5];
    const float* bih1 = (const float*)d_in[6];
    const float* bhh1 = (const float*)d_in[7];
    const float* Wih2 = (const float*)d_in[8];
    const float* Whh2 = (const float*)d_in[9];
    const float* bih2 = (const float*)d_in[10];
    const float* bhh2 = (const float*)d_in[11];
    const float* Wih3 = (const float*)d_in[12];
    const float* Whh3 = (const float*)d_in[13];
    const float* bih3 = (const float*)d_in[14];
    const float* bhh3 = (const float*)d_in[15];
    const float* W1   = (const float*)d_in[16];
    const float* b1   = (const float*)d_in[17];
    const float* W2   = (const float*)d_in[18];
    const float* b2   = (const float*)d_in[19];
    float* out = (float*)d_out;

    cudaFuncSetAttribute(k_rnn,  cudaFuncAttributeMaxDynamicSharedMemorySize, 163840);
    cudaFuncSetAttribute(k_mlp1, cudaFuncAttributeMaxDynamicSharedMemorySize, 65536);

    // prep
    k_init_state<<<64, 256>>>(h0);
    k_transpose<<<dim3(8, 8), dim3(32, 8)>>>(W1, H_S, H_S, 0);                 // W1t
    k_transpose<<<dim3(8, (V_S + 31) / 32), dim3(32, 8)>>>(W2, V_S, H_S, 1);   // W2t
    k_embed<<<dim3(G_S / 4, T_S), 256>>>(x, emb, Wih1, bih1, bhh1);

    // fused persistent recurrence (one launch for all 128 steps x 3 layers)
    k_rnn<<<RNN_BLOCKS, RNN_THREADS, 163840>>>(Whh1, Wih2, Whh2, Wih3, Whh3,
                                               bih2, bhh2, bih3, bhh3, c0);

    // batched head
    k_mlp1<<<T_S, 256, 65536>>>(b1);
    k_out<<<dim3((V_S + BN - 1) / BN, NT / BM), 256>>>(b2, out);

    if ((long long)out_size > NTV)
        k_labels<<<(NT + 255) / 256, 256>>>(x, out, (long long)out_size);
}

// round 9
// speedup vs baseline: 2.5393x; 1.0090x over previous
#include <cuda_runtime.h>
#include <math.h>
#include <stdint.h>

// Problem dims (fixed by reference)
#define N_B 64      // batch
#define T_S 128     // timesteps
#define V_S 20000   // vocab
#define E_S 16      // embed dim
#define H_S 256     // hidden
#define G_S 1024    // 4*H gates
#define NT  (N_B * T_S)          // 8192 rows
#define NTV ((long long)NT * V_S)

#define RNN_BLOCKS 64
#define RNN_THREADS 128

// ---------------- device scratch (no cudaMalloc allowed) ----------------
__device__ float g_g1pre[(size_t)T_S * G_S * N_B];     // [t][j][n]   32 MB
__device__ float g_h1a[H_S * N_B], g_h1b[H_S * N_B];   // states [k][n]
__device__ float g_h2a[H_S * N_B], g_h2b[H_S * N_B];
__device__ float g_h3seq[(size_t)(T_S + 1) * H_S * N_B]; // slot s = h3 after step s-1, [k][n]
__device__ float g_R[(size_t)NT * H_S];                // [row][k] row=n*T+t
__device__ float g_W1t[H_S * H_S];                     // [k][j]
__device__ float g_W2t[(size_t)H_S * V_S];             // [k][j]   20.5 MB
__device__ unsigned g_bar[2 * T_S + 1];                // grid-barrier counters (zero-init; block 0 resets at end)

// ---------------- helpers ----------------
__device__ __forceinline__ float sigf(float x) { return __fdividef(1.0f, 1.0f + __expf(-x)); }

// packed fp32x2 FMA (Blackwell FFMA2; only reachable via PTX fma.rn.f32x2)
__device__ __forceinline__ void ffma2(unsigned long long& d, unsigned long long a,
                                      unsigned long long b) {
    asm("fma.rn.f32x2 %0, %1, %2, %0;" : "+l"(d) : "l"(a), "l"(b));
}
__device__ __forceinline__ unsigned long long pk2dup(float x) {
    unsigned long long r;
    asm("mov.b64 %0, {%1, %1};" : "=l"(r) : "f"(x));
    return r;
}
__device__ __forceinline__ float2 u2f(unsigned long long v) {
    float2 f;
    asm("mov.b64 {%0, %1}, %2;" : "=f"(f.x), "=f"(f.y) : "l"(v));
    return f;
}
__device__ __forceinline__ unsigned long long f2u(float x, float y) {
    unsigned long long v;
    asm("mov.b64 %0, {%1, %2};" : "=l"(v) : "f"(x), "f"(y));
    return v;
}
// 16-byte activation load bypassing L1 (cross-block-produced data), as 2 packed pairs
__device__ __forceinline__ ulonglong2 ldcg128(const float* p) {
    ulonglong2 v;
    asm volatile("ld.global.cg.v2.u64 {%0, %1}, [%2];" : "=l"(v.x), "=l"(v.y) : "l"(p));
    return v;
}

// software grid barrier across the 64 co-resident blocks.
// Release: fence + arrive. Acquire: spin until count==RNN_BLOCKS, fence, bar.
// Each counter is used exactly once per run; final barrier is arrive-only (see k_rnn).
__device__ __forceinline__ void gbar(unsigned idx) {
    __threadfence();
    __syncthreads();
    if (threadIdx.x == 0) {
        atomicAdd(&g_bar[idx], 1u);
        while (((volatile unsigned*)g_bar)[idx] < (unsigned)RNN_BLOCKS) { }
        __threadfence();   // acquire side
    }
    __syncthreads();
}

// ---------------- prep kernels ----------------
__global__ void k_init_state(const float* __restrict__ h0) {
    int i = blockIdx.x * 256 + threadIdx.x;   // grid 64
    if (i >= H_S * N_B) return;
    int k = i / N_B, n = i % N_B;
    float h = h0[n * H_S + k];
    g_h1a[i] = h; g_h2a[i] = h; g_h3seq[i] = h;   // h3seq slot 0
}

// tiled transpose: in[rows][cols] -> out[cols][rows]; which: 0 = W1t, 1 = W2t
__global__ void k_transpose(const float* __restrict__ in, int rows, int cols, int which) {
    float* out = which ? g_W2t : g_W1t;
    __shared__ float tile[32][33];
    int c0 = blockIdx.x * 32, r0 = blockIdx.y * 32;
    int tx = threadIdx.x, ty = threadIdx.y;   // 32 x 8
#pragma unroll
    for (int i = 0; i < 32; i += 8) {
        int r = r0 + ty + i, c = c0 + tx;
        if (r < rows && c < cols) tile[ty + i][tx] = in[(size_t)r * cols + c];
    }
    __syncthreads();
#pragma unroll
    for (int i = 0; i < 32; i += 8) {
        int c = c0 + ty + i, r = r0 + tx;
        if (r < rows && c < cols) out[(size_t)c * rows + r] = tile[tx][ty + i];
    }
}

// g1pre[t][j][n] = bih1[j] + bhh1[j] + sum_e emb[x[n,t],e] * Wih1[j,e]
__global__ __launch_bounds__(256) void k_embed(const int* __restrict__ x,
                                               const float* __restrict__ emb,
                                               const float* __restrict__ Wih1,
                                               const float* __restrict__ bih1,
                                               const float* __restrict__ bhh1) {
    __shared__ float es[N_B][E_S + 1];
    __shared__ int xs[N_B];
    const int t = blockIdx.y;
    const int tid = threadIdx.x;
    if (tid < N_B) xs[tid] = x[tid * T_S + t];
    __syncthreads();
    for (int i = tid; i < N_B * E_S; i += 256) {
        int nn = i >> 4, e = i & 15;
        es[nn][e] = emb[(size_t)xs[nn] * E_S + e];
    }
    __syncthreads();
    const int n = tid & 63;
    const int j = blockIdx.x * 4 + (tid >> 6);
    float acc = bih1[j] + bhh1[j];
    const float* w = Wih1 + j * E_S;
#pragma unroll
    for (int e = 0; e < E_S; e++) acc = fmaf(es[n][e], w[e], acc);
    g_g1pre[((size_t)t * G_S + j) * N_B + n] = acc;
}

// ---------------- persistent fused 3-layer LSTM kernel ----------------
// 64 blocks x 128 threads. Warp w handles H-row jh = 4*block + w (all 4 gates).
// Lane l: n-quad q = l & 15 (covers n4 = 4q .. 4q+3); k-half kh = l >> 4
// (lanes 0-15 accumulate k in [0,128), lanes 16-31 k in [128,256)); the two
// halves are combined with shfl + add.f32x2, and lanes 0-15 finalize.
// Weights (f32x2-duplicated) live in 160KB dynamic SMEM for the whole run;
// c-states live in registers; h-states go through L2 (.cg) with software
// grid barriers.
//
// Barrier schedule per step t:  L1 -> gbar(2t) -> L2 -> gbar(2t+1) -> L3.
// No barrier after L3: any block's arrival at gbar(2t+2) is program-ordered
// after its own L3(t), so all L3(t) stores are visible (fence in gbar) before
// anyone starts L2(t+1)/L3(t+1). WAR on ping-pong h1/h2 buffers is covered
// by the same chain.

__device__ __forceinline__ void mat_acc2(const float* __restrict__ acts,
                                         const unsigned long long* __restrict__ wd,
                                         int kbase, int n4, unsigned long long acc[8]) {
#pragma unroll 4
    for (int k2 = 0; k2 < 64; ++k2) {    // 2 k per iter, 128 k per half-warp
        const int k = kbase + 2 * k2;
        ulonglong2 a0 = ldcg128(acts + (size_t)k * N_B + n4);        // (n4,n4+1),(n4+2,n4+3)
        ulonglong2 a1 = ldcg128(acts + (size_t)(k + 1) * N_B + n4);
#pragma unroll
        for (int g = 0; g < 4; ++g) {
            ulonglong2 w2 = *(const ulonglong2*)(wd + g * H_S + k);  // dup(w[k]), dup(w[k+1])
            ffma2(acc[2 * g + 0], w2.x, a0.x);
            ffma2(acc[2 * g + 1], w2.x, a0.y);
            ffma2(acc[2 * g + 0], w2.y, a1.x);
            ffma2(acc[2 * g + 1], w2.y, a1.y);
        }
    }
}

// sum the two k-halves: lane l += lane l+16 (valid in lanes 0-15 afterwards)
__device__ __forceinline__ void combine_halves(unsigned long long acc[8]) {
#pragma unroll
    for (int i = 0; i < 8; ++i) {
        unsigned lo = __shfl_down_sync(0xffffffffu, (unsigned)(acc[i] & 0xffffffffull), 16);
        unsigned hi = __shfl_down_sync(0xffffffffu, (unsigned)(acc[i] >> 32), 16);
        unsigned long long o = ((unsigned long long)hi << 32) | lo;
        asm("add.rn.f32x2 %0, %0, %1;" : "+l"(acc[i]) : "l"(o));
    }
}

// gate nonlinearity + c update + packed 16B h store (lanes 0-15 only)
__device__ __forceinline__ void cellfin2(const unsigned long long acc[8],
                                         unsigned long long cpk[2],
                                         float* __restrict__ hout, int jh, int n4) {
    float h[4];
#pragma unroll
    for (int p = 0; p < 2; ++p) {
        float2 ai = u2f(acc[0 + p]), af = u2f(acc[2 + p]);
        float2 ag = u2f(acc[4 + p]), ao = u2f(acc[6 + p]);
        float2 c = u2f(cpk[p]);
        float cx = sigf(af.x) * c.x + sigf(ai.x) * tanhf(ag.x);
        float cy = sigf(af.y) * c.y + sigf(ai.y) * tanhf(ag.y);
        cpk[p] = f2u(cx, cy);
        h[2 * p + 0] = sigf(ao.x) * tanhf(cx);
        h[2 * p + 1] = sigf(ao.y) * tanhf(cy);
    }
    asm volatile("st.global.cg.v4.f32 [%0], {%1, %2, %3, %4};"
                 :: "l"(hout + jh * N_B + n4), "f"(h[0]), "f"(h[1]), "f"(h[2]), "f"(h[3])
                 : "memory");
}

__global__ __launch_bounds__(RNN_THREADS, 1) void k_rnn(
    const float* __restrict__ Whh1,
    const float* __restrict__ Wih2, const float* __restrict__ Whh2,
    const float* __restrict__ Wih3, const float* __restrict__ Whh3,
    const float* __restrict__ bih2, const float* __restrict__ bhh2,
    const float* __restrict__ bih3, const float* __restrict__ bhh3,
    const float* __restrict__ c0) {
    extern __shared__ unsigned long long wsd[];   // [5][4 warps][4 gates][256 k] dup pairs
    const int tid  = threadIdx.x;
    const int w    = tid >> 5;
    const int lane = tid & 31;
    const int n4   = (lane & 15) * 4;     // n-quad base
    const int kh   = lane >> 4;           // k-half: 0 or 1
    const int kb   = kh * 128;            // k base for this half
    const int jh   = blockIdx.x * 4 + w;

    // NOTE: acc gate layout is acc[2*g + p]:
    //   acc[0],acc[1]=i(p0,p1)  acc[2],acc[3]=f  acc[4],acc[5]=g  acc[6],acc[7]=o
    // cellfin2 indexes acc[gate*2 + p] accordingly.

    // one-time weight preload, duplicated for f32x2 (coalesced LDG, linear STS)
    const float* Wsrc[5] = { Whh1, Wih2, Whh2, Wih3, Whh3 };
    for (int idx = tid; idx < 5 * 4 * 4 * H_S; idx += RNN_THREADS) {
        int mat  = idx >> 12;
        int ww   = (idx >> 10) & 3;
        int gate = (idx >> 8) & 3;
        int k    = idx & 255;
        float v = __ldg(Wsrc[mat] + (size_t)(gate * H_S + blockIdx.x * 4 + ww) * H_S + k);
        wsd[idx] = pk2dup(v);
    }
    // bias sums (packed, duplicated) and register-resident c states (lanes<16)
    unsigned long long b2[4], b3[4];
#pragma unroll
    for (int g = 0; g < 4; ++g) {
        b2[g] = pk2dup(bih2[g * H_S + jh] + bhh2[g * H_S + jh]);
        b3[g] = pk2dup(bih3[g * H_S + jh] + bhh3[g * H_S + jh]);
    }
    unsigned long long c1[2], c2[2], c3[2];
    if (kh == 0) {
        c1[0] = f2u(c0[(n4 + 0) * H_S + jh], c0[(n4 + 1) * H_S + jh]);
        c1[1] = f2u(c0[(n4 + 2) * H_S + jh], c0[(n4 + 3) * H_S + jh]);
        c2[0] = c1[0]; c2[1] = c1[1];
        c3[0] = c1[0]; c3[1] = c1[1];
    }
    __syncthreads();

    const unsigned long long* wd1  = wsd + ((0 * 4 + w) * 4) * H_S;
    const unsigned long long* wdi2 = wsd + ((1 * 4 + w) * 4) * H_S;
    const unsigned long long* wdh2 = wsd + ((2 * 4 + w) * 4) * H_S;
    const unsigned long long* wdi3 = wsd + ((3 * 4 + w) * 4) * H_S;
    const unsigned long long* wdh3 = wsd + ((4 * 4 + w) * 4) * H_S;

    for (int t = 0; t < T_S; ++t) {
        const float* h1in  = (t & 1) ? g_h1b : g_h1a;
        float*       h1out = (t & 1) ? g_h1a : g_h1b;
        const float* h2in  = (t & 1) ? g_h2b : g_h2a;
        float*       h2out = (t & 1) ? g_h2a : g_h2b;
        const float* h3in  = g_h3seq + (size_t)t * (H_S * N_B);
        float*       h3out = g_h3seq + (size_t)(t + 1) * (H_S * N_B);

        // ---- layer 1 (input part precomputed in g_g1pre) ----
        {
            unsigned long long acc[8];
            if (kh == 0) {
                const float* pre = g_g1pre + (size_t)t * (G_S * N_B);
#pragma unroll
                for (int g = 0; g < 4; ++g) {
                    ulonglong2 pv = *(const ulonglong2*)(pre + (size_t)(g * H_S + jh) * N_B + n4);
                    acc[2 * g] = pv.x; acc[2 * g + 1] = pv.y;
                }
            } else {
#pragma unroll
                for (int i = 0; i < 8; ++i) acc[i] = 0ull;
            }
            mat_acc2(h1in, wd1, kb, n4, acc);
            combine_halves(acc);
            if (kh == 0) cellfin2(acc, c1, h1out, jh, n4);
        }
        gbar(2 * t);
        // ---- layer 2 ----
        {
            unsigned long long acc[8];
#pragma unroll
            for (int g = 0; g < 4; ++g) {
                acc[2 * g]     = (kh == 0) ? b2[g] : 0ull;
                acc[2 * g + 1] = (kh == 0) ? b2[g] : 0ull;
            }
            mat_acc2(h1out, wdi2, kb, n4, acc);
            mat_acc2(h2in,  wdh2, kb, n4, acc);
            combine_halves(acc);
            if (kh == 0) cellfin2(acc, c2, h2out, jh, n4);
        }
        gbar(2 * t + 1);
        // ---- layer 3 (no trailing barrier needed; see header comment) ----
        {
            unsigned long long acc[8];
#pragma unroll
            for (int g = 0; g < 4; ++g) {
                acc[2 * g]     = (kh == 0) ? b3[g] : 0ull;
                acc[2 * g + 1] = (kh == 0) ? b3[g] : 0ull;
            }
            mat_acc2(h2out, wdi3, kb, n4, acc);
            mat_acc2(h3in,  wdh3, kb, n4, acc);
            combine_halves(acc);
            if (kh == 0) cellfin2(acc, c3, h3out, jh, n4);
        }
    }

    // ---- final barrier: arrive-only for blocks 1..63; block 0 waits and
    // then single-handedly resets all counters. Exiting blocks never read
    // g_bar again, so the reset cannot race with a spinning waiter. ----
    __threadfence();
    __syncthreads();
    if (blockIdx.x != 0) {
        if (tid == 0) atomicAdd(&g_bar[2 * T_S], 1u);
        return;
    }
    if (tid == 0) {
        atomicAdd(&g_bar[2 * T_S], 1u);
        while (((volatile unsigned*)g_bar)[2 * T_S] < (unsigned)RNN_BLOCKS) { }
        __threadfence();
    }
    __syncthreads();
    for (int i = tid; i <= 2 * T_S; i += RNN_THREADS) g_bar[i] = 0;
}

// ---------------- MLP layer 1 (+ReLU), block per timestep ----------------
// R[n*T+t][j] = relu(sum_k h3seq[t+1][k][n] * W1t[k][j] + b1[j])
__global__ __launch_bounds__(256) void k_mlp1(const float* __restrict__ b1) {
    extern __shared__ float hs[];             // [256 k][64 n] = 64KB
    const int t = blockIdx.x;
    const int j = threadIdx.x;
    const float4* src = (const float4*)(g_h3seq + (size_t)(t + 1) * (H_S * N_B));
    float4* hs4 = (float4*)hs;
    for (int i = j; i < H_S * N_B / 4; i += 256) hs4[i] = src[i];
    __syncthreads();
    float bb = b1[j];
#pragma unroll 1
    for (int pass = 0; pass < 4; ++pass) {
        float acc[16];
#pragma unroll
        for (int i = 0; i < 16; ++i) acc[i] = 0.0f;
#pragma unroll 4
        for (int k = 0; k < H_S; ++k) {
            float wv = g_W1t[k * H_S + j];
            const float4* hp = (const float4*)(hs + k * N_B + pass * 16);
            float4 h0 = hp[0], h1 = hp[1], h2 = hp[2], h3 = hp[3];
            acc[0]  = fmaf(h0.x, wv, acc[0]);  acc[1]  = fmaf(h0.y, wv, acc[1]);
            acc[2]  = fmaf(h0.z, wv, acc[2]);  acc[3]  = fmaf(h0.w, wv, acc[3]);
            acc[4]  = fmaf(h1.x, wv, acc[4]);  acc[5]  = fmaf(h1.y, wv, acc[5]);
            acc[6]  = fmaf(h1.z, wv, acc[6]);  acc[7]  = fmaf(h1.w, wv, acc[7]);
            acc[8]  = fmaf(h2.x, wv, acc[8]);  acc[9]  = fmaf(h2.y, wv, acc[9]);
            acc[10] = fmaf(h2.z, wv, acc[10]); acc[11] = fmaf(h2.w, wv, acc[11]);
            acc[12] = fmaf(h3.x, wv, acc[12]); acc[13] = fmaf(h3.y, wv, acc[13]);
            acc[14] = fmaf(h3.z, wv, acc[14]); acc[15] = fmaf(h3.w, wv, acc[15]);
        }
#pragma unroll
        for (int i = 0; i < 16; ++i) {
            int n = pass * 16 + i;
            float v = acc[i] + bb;
            g_R[((size_t)n * T_S + t) * H_S + j] = v > 0.0f ? v : 0.0f;
        }
    }
}

// ---------------- vocab projection: C[8192,20000] = R @ W2t + b2 ----------------
#define BM 128
#define BN 128
#define BK 16
__global__ __launch_bounds__(256, 2) void k_out(const float* __restrict__ b2,
                                                float* __restrict__ C) {
    __shared__ float As[BK][BM];   // [k][m]
    __shared__ float Bs[BK][BN];   // [k][n]
    const int tid = threadIdx.x;
    const int bn = blockIdx.x * BN;
    const int bm = blockIdx.y * BM;
    const int tx = tid & 15, ty = tid >> 4;
    const int m0 = ty * 8, n0 = tx * 8;

    unsigned long long acc[8][4];
#pragma unroll
    for (int i = 0; i < 8; ++i)
#pragma unroll
        for (int j = 0; j < 4; ++j) acc[i][j] = 0ull;

    for (int k0 = 0; k0 < H_S; k0 += BK) {
#pragma unroll
        for (int s = tid; s < (BM * BK) / 4; s += 256) {
            int row = s >> 2, kq = (s & 3) << 2;
            float4 v = *(const float4*)(g_R + (size_t)(bm + row) * H_S + k0 + kq);
            As[kq + 0][row] = v.x; As[kq + 1][row] = v.y;
            As[kq + 2][row] = v.z; As[kq + 3][row] = v.w;
        }
#pragma unroll
        for (int s = tid; s < (BK * BN) / 4; s += 256) {
            int kr = s >> 5, cq = (s & 31) << 2;
            int col = bn + cq;
            float4 v = make_float4(0.f, 0.f, 0.f, 0.f);
            if (col < V_S) v = *(const float4*)(g_W2t + (size_t)(k0 + kr) * V_S + col);
            *(float4*)&Bs[kr][cq] = v;
        }
        __syncthreads();
#pragma unroll
        for (int k = 0; k < BK; ++k) {
            float4 a0 = *(const float4*)&As[k][m0];
            float4 a1 = *(const float4*)&As[k][m0 + 4];
            ulonglong2 bb0 = *(const ulonglong2*)&Bs[k][n0];
            ulonglong2 bb1 = *(const ulonglong2*)&Bs[k][n0 + 4];
            unsigned long long br[4] = { bb0.x, bb0.y, bb1.x, bb1.y };
            float ar[8] = { a0.x, a0.y, a0.z, a0.w, a1.x, a1.y, a1.z, a1.w };
#pragma unroll
            for (int i = 0; i < 8; ++i) {
                unsigned long long ad = pk2dup(ar[i]);
#pragma unroll
                for (int j = 0; j < 4; ++j) ffma2(acc[i][j], ad, br[j]);
            }
        }
        __syncthreads();
    }
#pragma unroll
    for (int i = 0; i < 8; ++i) {
        size_t rowoff = (size_t)(bm + m0 + i) * V_S;
#pragma unroll
        for (int jq = 0; jq < 2; ++jq) {
            int col = bn + n0 + jq * 4;
            if (col < V_S) {
                float4 bias = *(const float4*)(b2 + col);
                float2 p0 = u2f(acc[i][jq * 2]);
                float2 p1 = u2f(acc[i][jq * 2 + 1]);
                float4 o = make_float4(p0.x + bias.x, p0.y + bias.y,
                                       p1.x + bias.z, p1.y + bias.w);
                *(float4*)(C + rowoff + col) = o;
            }
        }
    }
}

// labels (second reference output, cast to output dtype)
__global__ void k_labels(const int* __restrict__ x, float* __restrict__ out, long long out_size) {
    int i = blockIdx.x * 256 + threadIdx.x;
    if (i < NT && NTV + i < out_size) out[NTV + i] = (float)x[i];
}

// ---------------- host launcher ----------------
extern "C" void kernel_launch(void* const* d_in, const int* in_sizes, int n_in,
                              void* d_out, int out_size) {
    const int*   x    = (const int*)d_in[0];
    const float* h0   = (const float*)d_in[1];
    const float* c0   = (const float*)d_in[2];
    const float* emb  = (const float*)d_in[3];
    const float* Wih1 = (const float*)d_in[4];
    const float* Whh1 = (const float*)d_in[5];
    const float* bih1 = (const float*)d_in[6];
    const float* bhh1 = (const float*)d_in[7];
    const float* Wih2 = (const float*)d_in[8];
    const float* Whh2 = (const float*)d_in[9];
    const float* bih2 = (const float*)d_in[10];
    const float* bhh2 = (const float*)d_in[11];
    const float* Wih3 = (const float*)d_in[12];
    const float* Whh3 = (const float*)d_in[13];
    const float* bih3 = (const float*)d_in[14];
    const float* bhh3 = (const float*)d_in[15];
    const float* W1   = (const float*)d_in[16];
    const float* b1   = (const float*)d_in[17];
    const float* W2   = (const float*)d_in[18];
    const float* b2   = (const float*)d_in[19];
    float* out = (float*)d_out;

    cudaFuncSetAttribute(k_rnn,  cudaFuncAttributeMaxDynamicSharedMemorySize, 163840);
    cudaFuncSetAttribute(k_mlp1, cudaFuncAttributeMaxDynamicSharedMemorySize, 65536);

    // prep
    k_init_state<<<64, 256>>>(h0);
    k_transpose<<<dim3(8, 8), dim3(32, 8)>>>(W1, H_S, H_S, 0);                 // W1t
    k_transpose<<<dim3(8, (V_S + 31) / 32), dim3(32, 8)>>>(W2, V_S, H_S, 1);   // W2t
    k_embed<<<dim3(G_S / 4, T_S), 256>>>(x, emb, Wih1, bih1, bhh1);

    // fused persistent recurrence (one launch for all 128 steps x 3 layers)
    k_rnn<<<RNN_BLOCKS, RNN_THREADS, 163840>>>(Whh1, Wih2, Whh2, Wih3, Whh3,
                                               bih2, bhh2, bih3, bhh3, c0);

    // batched head
    k_mlp1<<<T_S, 256, 65536>>>(b1);
    k_out<<<dim3((V_S + BN - 1) / BN, NT / BM), 256>>>(b2, out);

    if ((long long)out_size > NTV)
        k_labels<<<(NT + 255) / 256, 256>>>(x, out, (long long)out_size);
}

// round 10
// speedup vs baseline: 3.0153x; 1.1874x over previous
#include <cuda_runtime.h>
#include <math.h>
#include <stdint.h>

// Problem dims (fixed by reference)
#define N_B 64      // batch
#define T_S 128     // timesteps
#define V_S 20000   // vocab
#define E_S 16      // embed dim
#define H_S 256     // hidden
#define G_S 1024    // 4*H gates
#define NT  (N_B * T_S)          // 8192 rows
#define NTV ((long long)NT * V_S)

#define RNN_BLOCKS 64
#define RNN_THREADS 128

// dynamic SMEM: [weights dup 163840 B][act buffer 65536 B]
#define WSD_U64   (5 * 4 * 4 * H_S)          // 20480 u64 = 163840 B
#define SMEM_RNN  (163840 + 65536)           // 229376 <= 232448 max opt-in

// ---------------- device scratch (no cudaMalloc allowed) ----------------
__device__ float g_g1pre[(size_t)T_S * G_S * N_B];     // [t][j][n]   32 MB
__device__ float g_h1a[H_S * N_B], g_h1b[H_S * N_B];   // states [k][n]
__device__ float g_h2a[H_S * N_B], g_h2b[H_S * N_B];
__device__ float g_h3seq[(size_t)(T_S + 1) * H_S * N_B]; // slot s = h3 after step s-1, [k][n]
__device__ float g_R[(size_t)NT * H_S];                // [row][k] row=n*T+t
__device__ float g_W1t[H_S * H_S];                     // [k][j]
__device__ float g_W2t[(size_t)H_S * V_S];             // [k][j]   20.5 MB
__device__ unsigned g_bar[2 * T_S + 1];                // grid-barrier counters (zero-init; block 0 resets at end)

// ---------------- helpers ----------------
__device__ __forceinline__ float sigf(float x) { return __fdividef(1.0f, 1.0f + __expf(-x)); }

// packed fp32x2 FMA (Blackwell FFMA2; only reachable via PTX fma.rn.f32x2)
__device__ __forceinline__ void ffma2(unsigned long long& d, unsigned long long a,
                                      unsigned long long b) {
    asm("fma.rn.f32x2 %0, %1, %2, %0;" : "+l"(d) : "l"(a), "l"(b));
}
__device__ __forceinline__ unsigned long long pk2dup(float x) {
    unsigned long long r;
    asm("mov.b64 %0, {%1, %1};" : "=l"(r) : "f"(x));
    return r;
}
__device__ __forceinline__ float2 u2f(unsigned long long v) {
    float2 f;
    asm("mov.b64 {%0, %1}, %2;" : "=f"(f.x), "=f"(f.y) : "l"(v));
    return f;
}
__device__ __forceinline__ unsigned long long f2u(float x, float y) {
    unsigned long long v;
    asm("mov.b64 %0, {%1, %2};" : "=l"(v) : "f"(x), "f"(y));
    return v;
}
// 16-byte L1-bypassing global load (cross-block-produced data must not hit stale L1)
__device__ __forceinline__ float4 ldcg_f4(const float* p) {
    float4 v;
    asm volatile("ld.global.cg.v4.f32 {%0, %1, %2, %3}, [%4];"
                 : "=f"(v.x), "=f"(v.y), "=f"(v.z), "=f"(v.w) : "l"(p));
    return v;
}

// software grid barrier across the 64 co-resident blocks.
// Release: fence + arrive. Acquire: spin until count==RNN_BLOCKS, fence, bar.
// Each counter is used exactly once per run; final barrier is arrive-only (see k_rnn).
__device__ __forceinline__ void gbar(unsigned idx) {
    __threadfence();
    __syncthreads();
    if (threadIdx.x == 0) {
        atomicAdd(&g_bar[idx], 1u);
        while (((volatile unsigned*)g_bar)[idx] < (unsigned)RNN_BLOCKS) { }
        __threadfence();   // acquire side
    }
    __syncthreads();
}

// cooperative stage of one act matrix (256 k x 64 n = 64KB) global -> SMEM.
// Caller guarantees no thread is still READING the buffer (sync before call).
// Trailing __syncthreads publishes the staged data.
__device__ __forceinline__ void stage_acts(float* __restrict__ buf,
                                           const float* __restrict__ src, int tid) {
#pragma unroll 8
    for (int i = 0; i < (H_S * N_B / 4) / RNN_THREADS; ++i) {   // 32 float4 per thread
        int idx = tid + i * RNN_THREADS;
        *(float4*)(buf + 4 * idx) = ldcg_f4(src + 4 * idx);
    }
    __syncthreads();
}

// ---------------- prep kernels ----------------
__global__ void k_init_state(const float* __restrict__ h0) {
    int i = blockIdx.x * 256 + threadIdx.x;   // grid 64
    if (i >= H_S * N_B) return;
    int k = i / N_B, n = i % N_B;
    float h = h0[n * H_S + k];
    g_h1a[i] = h; g_h2a[i] = h; g_h3seq[i] = h;   // h3seq slot 0
}

// tiled transpose: in[rows][cols] -> out[cols][rows]; which: 0 = W1t, 1 = W2t
__global__ void k_transpose(const float* __restrict__ in, int rows, int cols, int which) {
    float* out = which ? g_W2t : g_W1t;
    __shared__ float tile[32][33];
    int c0 = blockIdx.x * 32, r0 = blockIdx.y * 32;
    int tx = threadIdx.x, ty = threadIdx.y;   // 32 x 8
#pragma unroll
    for (int i = 0; i < 32; i += 8) {
        int r = r0 + ty + i, c = c0 + tx;
        if (r < rows && c < cols) tile[ty + i][tx] = in[(size_t)r * cols + c];
    }
    __syncthreads();
#pragma unroll
    for (int i = 0; i < 32; i += 8) {
        int c = c0 + ty + i, r = r0 + tx;
        if (r < rows && c < cols) out[(size_t)c * rows + r] = tile[tx][ty + i];
    }
}

// g1pre[t][j][n] = bih1[j] + bhh1[j] + sum_e emb[x[n,t],e] * Wih1[j,e]
__global__ __launch_bounds__(256) void k_embed(const int* __restrict__ x,
                                               const float* __restrict__ emb,
                                               const float* __restrict__ Wih1,
                                               const float* __restrict__ bih1,
                                               const float* __restrict__ bhh1) {
    __shared__ float es[N_B][E_S + 1];
    __shared__ int xs[N_B];
    const int t = blockIdx.y;
    const int tid = threadIdx.x;
    if (tid < N_B) xs[tid] = x[tid * T_S + t];
    __syncthreads();
    for (int i = tid; i < N_B * E_S; i += 256) {
        int nn = i >> 4, e = i & 15;
        es[nn][e] = emb[(size_t)xs[nn] * E_S + e];
    }
    __syncthreads();
    const int n = tid & 63;
    const int j = blockIdx.x * 4 + (tid >> 6);
    float acc = bih1[j] + bhh1[j];
    const float* w = Wih1 + j * E_S;
#pragma unroll
    for (int e = 0; e < E_S; e++) acc = fmaf(es[n][e], w[e], acc);
    g_g1pre[((size_t)t * G_S + j) * N_B + n] = acc;
}

// ---------------- persistent fused 3-layer LSTM kernel ----------------
// 64 blocks x 128 threads. Warp w handles H-row jh = 4*block + w (all 4 gates).
// Lane l: n-quad q = l & 15 (n4 = 4q..4q+3); k-half kh = l >> 4; halves are
// combined with shfl + add.f32x2 and lanes 0-15 finalize.
// Weights (f32x2-duplicated, 160KB) + one act staging buffer (64KB) live in
// dynamic SMEM. Each act matrix is loaded from L2 ONCE per block (cooperative
// .cg stage) instead of once per warp -> 4x less L2 traffic, LDS-fed FFMA2.
//
// Barrier schedule per step t:  L1 -> gbar(2t) -> L2 -> gbar(2t+1) -> L3.
// No gbar after L3 (see step-chain argument in earlier rounds); the loop-top
// __syncthreads protects the staging buffer WAR within the block.

__device__ __forceinline__ void mat_acc_s(const float* __restrict__ ab,
                                          const unsigned long long* __restrict__ wd,
                                          int kbase, int n4, unsigned long long acc[8]) {
#pragma unroll 4
    for (int k2 = 0; k2 < 64; ++k2) {    // 2 k per iter, 128 k per half-warp
        const int k = kbase + 2 * k2;
        ulonglong2 a0 = *(const ulonglong2*)(ab + (size_t)k * N_B + n4);
        ulonglong2 a1 = *(const ulonglong2*)(ab + (size_t)(k + 1) * N_B + n4);
#pragma unroll
        for (int g = 0; g < 4; ++g) {
            ulonglong2 w2 = *(const ulonglong2*)(wd + g * H_S + k);  // dup(w[k]), dup(w[k+1])
            ffma2(acc[2 * g + 0], w2.x, a0.x);
            ffma2(acc[2 * g + 1], w2.x, a0.y);
            ffma2(acc[2 * g + 0], w2.y, a1.x);
            ffma2(acc[2 * g + 1], w2.y, a1.y);
        }
    }
}

// sum the two k-halves: lane l += lane l+16 (valid in lanes 0-15 afterwards)
__device__ __forceinline__ void combine_halves(unsigned long long acc[8]) {
#pragma unroll
    for (int i = 0; i < 8; ++i) {
        unsigned lo = __shfl_down_sync(0xffffffffu, (unsigned)(acc[i] & 0xffffffffull), 16);
        unsigned hi = __shfl_down_sync(0xffffffffu, (unsigned)(acc[i] >> 32), 16);
        unsigned long long o = ((unsigned long long)hi << 32) | lo;
        asm("add.rn.f32x2 %0, %0, %1;" : "+l"(acc[i]) : "l"(o));
    }
}

// gate nonlinearity + c update + packed 16B h store (lanes 0-15 only)
__device__ __forceinline__ void cellfin2(const unsigned long long acc[8],
                                         unsigned long long cpk[2],
                                         float* __restrict__ hout, int jh, int n4) {
    float h[4];
#pragma unroll
    for (int p = 0; p < 2; ++p) {
        float2 ai = u2f(acc[0 + p]), af = u2f(acc[2 + p]);
        float2 ag = u2f(acc[4 + p]), ao = u2f(acc[6 + p]);
        float2 c = u2f(cpk[p]);
        float cx = sigf(af.x) * c.x + sigf(ai.x) * tanhf(ag.x);
        float cy = sigf(af.y) * c.y + sigf(ai.y) * tanhf(ag.y);
        cpk[p] = f2u(cx, cy);
        h[2 * p + 0] = sigf(ao.x) * tanhf(cx);
        h[2 * p + 1] = sigf(ao.y) * tanhf(cy);
    }
    asm volatile("st.global.cg.v4.f32 [%0], {%1, %2, %3, %4};"
                 :: "l"(hout + jh * N_B + n4), "f"(h[0]), "f"(h[1]), "f"(h[2]), "f"(h[3])
                 : "memory");
}

__global__ __launch_bounds__(RNN_THREADS, 1) void k_rnn(
    const float* __restrict__ Whh1,
    const float* __restrict__ Wih2, const float* __restrict__ Whh2,
    const float* __restrict__ Wih3, const float* __restrict__ Whh3,
    const float* __restrict__ bih2, const float* __restrict__ bhh2,
    const float* __restrict__ bih3, const float* __restrict__ bhh3,
    const float* __restrict__ c0) {
    extern __shared__ unsigned long long wsd[];   // [5][4 warps][4 gates][256 k] dup pairs
    float* ab = (float*)(wsd + WSD_U64);          // act staging buffer [256 k][64 n]
    const int tid  = threadIdx.x;
    const int w    = tid >> 5;
    const int lane = tid & 31;
    const int n4   = (lane & 15) * 4;     // n-quad base
    const int kh   = lane >> 4;           // k-half: 0 or 1
    const int kb   = kh * 128;            // k base for this half
    const int jh   = blockIdx.x * 4 + w;

    // acc gate layout: acc[2*g + p]  (g: 0=i,1=f,2=g,3=o ; p: n-pair half)

    // one-time weight preload, duplicated for f32x2 (coalesced LDG, linear STS)
    const float* Wsrc[5] = { Whh1, Wih2, Whh2, Wih3, Whh3 };
    for (int idx = tid; idx < 5 * 4 * 4 * H_S; idx += RNN_THREADS) {
        int mat  = idx >> 12;
        int ww   = (idx >> 10) & 3;
        int gate = (idx >> 8) & 3;
        int k    = idx & 255;
        float v = __ldg(Wsrc[mat] + (size_t)(gate * H_S + blockIdx.x * 4 + ww) * H_S + k);
        wsd[idx] = pk2dup(v);
    }
    // bias sums (packed, duplicated) and register-resident c states (lanes<16)
    unsigned long long b2[4], b3[4];
#pragma unroll
    for (int g = 0; g < 4; ++g) {
        b2[g] = pk2dup(bih2[g * H_S + jh] + bhh2[g * H_S + jh]);
        b3[g] = pk2dup(bih3[g * H_S + jh] + bhh3[g * H_S + jh]);
    }
    unsigned long long c1[2], c2[2], c3[2];
    if (kh == 0) {
        c1[0] = f2u(c0[(n4 + 0) * H_S + jh], c0[(n4 + 1) * H_S + jh]);
        c1[1] = f2u(c0[(n4 + 2) * H_S + jh], c0[(n4 + 3) * H_S + jh]);
        c2[0] = c1[0]; c2[1] = c1[1];
        c3[0] = c1[0]; c3[1] = c1[1];
    }
    __syncthreads();

    const unsigned long long* wd1  = wsd + ((0 * 4 + w) * 4) * H_S;
    const unsigned long long* wdi2 = wsd + ((1 * 4 + w) * 4) * H_S;
    const unsigned long long* wdh2 = wsd + ((2 * 4 + w) * 4) * H_S;
    const unsigned long long* wdi3 = wsd + ((3 * 4 + w) * 4) * H_S;
    const unsigned long long* wdh3 = wsd + ((4 * 4 + w) * 4) * H_S;

    for (int t = 0; t < T_S; ++t) {
        const float* h1in  = (t & 1) ? g_h1b : g_h1a;
        float*       h1out = (t & 1) ? g_h1a : g_h1b;
        const float* h2in  = (t & 1) ? g_h2b : g_h2a;
        float*       h2out = (t & 1) ? g_h2a : g_h2b;
        const float* h3in  = g_h3seq + (size_t)t * (H_S * N_B);
        float*       h3out = g_h3seq + (size_t)(t + 1) * (H_S * N_B);

        // ---- layer 1 (input part precomputed in g_g1pre) ----
        __syncthreads();                       // buffer WAR vs previous step's L3 readers
        stage_acts(ab, h1in, tid);
        {
            unsigned long long acc[8];
            if (kh == 0) {
                const float* pre = g_g1pre + (size_t)t * (G_S * N_B);
#pragma unroll
                for (int g = 0; g < 4; ++g) {
                    ulonglong2 pv = *(const ulonglong2*)(pre + (size_t)(g * H_S + jh) * N_B + n4);
                    acc[2 * g] = pv.x; acc[2 * g + 1] = pv.y;
                }
            } else {
#pragma unroll
                for (int i = 0; i < 8; ++i) acc[i] = 0ull;
            }
            mat_acc_s(ab, wd1, kb, n4, acc);
            combine_halves(acc);
            if (kh == 0) cellfin2(acc, c1, h1out, jh, n4);
        }
        gbar(2 * t);                           // ends with __syncthreads -> buffer free
        // ---- layer 2 ----
        {
            unsigned long long acc[8];
#pragma unroll
            for (int g = 0; g < 4; ++g) {
                acc[2 * g]     = (kh == 0) ? b2[g] : 0ull;
                acc[2 * g + 1] = (kh == 0) ? b2[g] : 0ull;
            }
            stage_acts(ab, h1out, tid);
            mat_acc_s(ab, wdi2, kb, n4, acc);
            __syncthreads();                   // all readers done before restage
            stage_acts(ab, h2in, tid);
            mat_acc_s(ab, wdh2, kb, n4, acc);
            combine_halves(acc);
            if (kh == 0) cellfin2(acc, c2, h2out, jh, n4);
        }
        gbar(2 * t + 1);
        // ---- layer 3 (no trailing gbar; loop-top __syncthreads guards buffer) ----
        {
            unsigned long long acc[8];
#pragma unroll
            for (int g = 0; g < 4; ++g) {
                acc[2 * g]     = (kh == 0) ? b3[g] : 0ull;
                acc[2 * g + 1] = (kh == 0) ? b3[g] : 0ull;
            }
            stage_acts(ab, h2out, tid);
            mat_acc_s(ab, wdi3, kb, n4, acc);
            __syncthreads();
            stage_acts(ab, h3in, tid);
            mat_acc_s(ab, wdh3, kb, n4, acc);
            combine_halves(acc);
            if (kh == 0) cellfin2(acc, c3, h3out, jh, n4);
        }
    }

    // ---- final barrier: arrive-only for blocks 1..63; block 0 waits and
    // then single-handedly resets all counters. Exiting blocks never read
    // g_bar again, so the reset cannot race with a spinning waiter. ----
    __threadfence();
    __syncthreads();
    if (blockIdx.x != 0) {
        if (tid == 0) atomicAdd(&g_bar[2 * T_S], 1u);
        return;
    }
    if (tid == 0) {
        atomicAdd(&g_bar[2 * T_S], 1u);
        while (((volatile unsigned*)g_bar)[2 * T_S] < (unsigned)RNN_BLOCKS) { }
        __threadfence();
    }
    __syncthreads();
    for (int i = tid; i <= 2 * T_S; i += RNN_THREADS) g_bar[i] = 0;
}

// ---------------- MLP layer 1 (+ReLU), block per timestep ----------------
// R[n*T+t][j] = relu(sum_k h3seq[t+1][k][n] * W1t[k][j] + b1[j])
__global__ __launch_bounds__(256) void k_mlp1(const float* __restrict__ b1) {
    extern __shared__ float hs[];             // [256 k][64 n] = 64KB
    const int t = blockIdx.x;
    const int j = threadIdx.x;
    const float4* src = (const float4*)(g_h3seq + (size_t)(t + 1) * (H_S * N_B));
    float4* hs4 = (float4*)hs;
    for (int i = j; i < H_S * N_B / 4; i += 256) hs4[i] = src[i];
    __syncthreads();
    float bb = b1[j];
#pragma unroll 1
    for (int pass = 0; pass < 4; ++pass) {
        float acc[16];
#pragma unroll
        for (int i = 0; i < 16; ++i) acc[i] = 0.0f;
#pragma unroll 4
        for (int k = 0; k < H_S; ++k) {
            float wv = g_W1t[k * H_S + j];
            const float4* hp = (const float4*)(hs + k * N_B + pass * 16);
            float4 h0 = hp[0], h1 = hp[1], h2 = hp[2], h3 = hp[3];
            acc[0]  = fmaf(h0.x, wv, acc[0]);  acc[1]  = fmaf(h0.y, wv, acc[1]);
            acc[2]  = fmaf(h0.z, wv, acc[2]);  acc[3]  = fmaf(h0.w, wv, acc[3]);
            acc[4]  = fmaf(h1.x, wv, acc[4]);  acc[5]  = fmaf(h1.y, wv, acc[5]);
            acc[6]  = fmaf(h1.z, wv, acc[6]);  acc[7]  = fmaf(h1.w, wv, acc[7]);
            acc[8]  = fmaf(h2.x, wv, acc[8]);  acc[9]  = fmaf(h2.y, wv, acc[9]);
            acc[10] = fmaf(h2.z, wv, acc[10]); acc[11] = fmaf(h2.w, wv, acc[11]);
            acc[12] = fmaf(h3.x, wv, acc[12]); acc[13] = fmaf(h3.y, wv, acc[13]);
            acc[14] = fmaf(h3.z, wv, acc[14]); acc[15] = fmaf(h3.w, wv, acc[15]);
        }
#pragma unroll
        for (int i = 0; i < 16; ++i) {
            int n = pass * 16 + i;
            float v = acc[i] + bb;
            g_R[((size_t)n * T_S + t) * H_S + j] = v > 0.0f ? v : 0.0f;
        }
    }
}

// ---------------- vocab projection: C[8192,20000] = R @ W2t + b2 ----------------
#define BM 128
#define BN 128
#define BK 16
__global__ __launch_bounds__(256, 2) void k_out(const float* __restrict__ b2,
                                                float* __restrict__ C) {
    __shared__ float As[BK][BM];   // [k][m]
    __shared__ float Bs[BK][BN];   // [k][n]
    const int tid = threadIdx.x;
    const int bn = blockIdx.x * BN;
    const int bm = blockIdx.y * BM;
    const int tx = tid & 15, ty = tid >> 4;
    const int m0 = ty * 8, n0 = tx * 8;

    unsigned long long acc[8][4];
#pragma unroll
    for (int i = 0; i < 8; ++i)
#pragma unroll
        for (int j = 0; j < 4; ++j) acc[i][j] = 0ull;

    for (int k0 = 0; k0 < H_S; k0 += BK) {
#pragma unroll
        for (int s = tid; s < (BM * BK) / 4; s += 256) {
            int row = s >> 2, kq = (s & 3) << 2;
            float4 v = *(const float4*)(g_R + (size_t)(bm + row) * H_S + k0 + kq);
            As[kq + 0][row] = v.x; As[kq + 1][row] = v.y;
            As[kq + 2][row] = v.z; As[kq + 3][row] = v.w;
        }
#pragma unroll
        for (int s = tid; s < (BK * BN) / 4; s += 256) {
            int kr = s >> 5, cq = (s & 31) << 2;
            int col = bn + cq;
            float4 v = make_float4(0.f, 0.f, 0.f, 0.f);
            if (col < V_S) v = *(const float4*)(g_W2t + (size_t)(k0 + kr) * V_S + col);
            *(float4*)&Bs[kr][cq] = v;
        }
        __syncthreads();
#pragma unroll
        for (int k = 0; k < BK; ++k) {
            float4 a0 = *(const float4*)&As[k][m0];
            float4 a1 = *(const float4*)&As[k][m0 + 4];
            ulonglong2 bb0 = *(const ulonglong2*)&Bs[k][n0];
            ulonglong2 bb1 = *(const ulonglong2*)&Bs[k][n0 + 4];
            unsigned long long br[4] = { bb0.x, bb0.y, bb1.x, bb1.y };
            float ar[8] = { a0.x, a0.y, a0.z, a0.w, a1.x, a1.y, a1.z, a1.w };
#pragma unroll
            for (int i = 0; i < 8; ++i) {
                unsigned long long ad = pk2dup(ar[i]);
#pragma unroll
                for (int j = 0; j < 4; ++j) ffma2(acc[i][j], ad, br[j]);
            }
        }
        __syncthreads();
    }
#pragma unroll
    for (int i = 0; i < 8; ++i) {
        size_t rowoff = (size_t)(bm + m0 + i) * V_S;
#pragma unroll
        for (int jq = 0; jq < 2; ++jq) {
            int col = bn + n0 + jq * 4;
            if (col < V_S) {
                float4 bias = *(const float4*)(b2 + col);
                float2 p0 = u2f(acc[i][jq * 2]);
                float2 p1 = u2f(acc[i][jq * 2 + 1]);
                float4 o = make_float4(p0.x + bias.x, p0.y + bias.y,
                                       p1.x + bias.z, p1.y + bias.w);
                *(float4*)(C + rowoff + col) = o;
            }
        }
    }
}

// labels (second reference output, cast to output dtype)
__global__ void k_labels(const int* __restrict__ x, float* __restrict__ out, long long out_size) {
    int i = blockIdx.x * 256 + threadIdx.x;
    if (i < NT && NTV + i < out_size) out[NTV + i] = (float)x[i];
}

// ---------------- host launcher ----------------
extern "C" void kernel_launch(void* const* d_in, const int* in_sizes, int n_in,
                              void* d_out, int out_size) {
    const int*   x    = (const int*)d_in[0];
    const float* h0   = (const float*)d_in[1];
    const float* c0   = (const float*)d_in[2];
    const float* emb  = (const float*)d_in[3];
    const float* Wih1 = (const float*)d_in[4];
    const float* Whh1 = (const float*)d_in[5];
    const float* bih1 = (const float*)d_in[6];
    const float* bhh1 = (const float*)d_in[7];
    const float* Wih2 = (const float*)d_in[8];
    const float* Whh2 = (const float*)d_in[9];
    const float* bih2 = (const float*)d_in[10];
    const float* bhh2 = (const float*)d_in[11];
    const float* Wih3 = (const float*)d_in[12];
    const float* Whh3 = (const float*)d_in[13];
    const float* bih3 = (const float*)d_in[14];
    const float* bhh3 = (const float*)d_in[15];
    const float* W1   = (const float*)d_in[16];
    const float* b1   = (const float*)d_in[17];
    const float* W2   = (const float*)d_in[18];
    const float* b2   = (const float*)d_in[19];
    float* out = (float*)d_out;

    cudaFuncSetAttribute(k_rnn,  cudaFuncAttributeMaxDynamicSharedMemorySize, SMEM_RNN);
    cudaFuncSetAttribute(k_mlp1, cudaFuncAttributeMaxDynamicSharedMemorySize, 65536);

    // prep
    k_init_state<<<64, 256>>>(h0);
    k_transpose<<<dim3(8, 8), dim3(32, 8)>>>(W1, H_S, H_S, 0);                 // W1t
    k_transpose<<<dim3(8, (V_S + 31) / 32), dim3(32, 8)>>>(W2, V_S, H_S, 1);   // W2t
    k_embed<<<dim3(G_S / 4, T_S), 256>>>(x, emb, Wih1, bih1, bhh1);

    // fused persistent recurrence (one launch for all 128 steps x 3 layers)
    k_rnn<<<RNN_BLOCKS, RNN_THREADS, SMEM_RNN>>>(Whh1, Wih2, Whh2, Wih3, Whh3,
                                                 bih2, bhh2, bih3, bhh3, c0);

    // batched head
    k_mlp1<<<T_S, 256, 65536>>>(b1);
    k_out<<<dim3((V_S + BN - 1) / BN, NT / BM), 256>>>(b2, out);

    if ((long long)out_size > NTV)
        k_labels<<<(NT + 255) / 256, 256>>>(x, out, (long long)out_size);
}

// round 11
// speedup vs baseline: 4.1228x; 1.3673x over previous
#include <cuda_runtime.h>
#include <math.h>
#include <stdint.h>

// Problem dims (fixed by reference)
#define N_B 64      // batch
#define T_S 128     // timesteps
#define V_S 20000   // vocab
#define E_S 16      // embed dim
#define H_S 256     // hidden
#define G_S 1024    // 4*H gates
#define NT  (N_B * T_S)          // 8192 rows
#define NTV ((long long)NT * V_S)

// wavefront-pipelined persistent RNN: 3 layer-groups x 32 blocks
#define GRP_BLOCKS 32
#define RNN_BLOCKS (3 * GRP_BLOCKS)      // 96
#define RNN_THREADS 256                  // 8 warps; warp = one H-row (jh)
#define WAVES (T_S + 2)                  // 130
#define NBAR  (WAVES)                    // counters: waves 0..128 + final at 129

// dynamic SMEM: [weights dup <=131072 B][act buffer 65536 B]
#define WSD_U64   (2 * 8 * 4 * H_S)      // 16384 u64 = 131072 B (2 matrices max)
#define SMEM_RNN  (131072 + 65536)       // 196608

// ---------------- device scratch (no cudaMalloc allowed) ----------------
__device__ float g_g1pre[(size_t)T_S * G_S * N_B];     // [t][j][n]   32 MB
__device__ float g_h1a[H_S * N_B], g_h1b[H_S * N_B];   // states [k][n]; h(t) in a if t odd, b if t even
__device__ float g_h2a[H_S * N_B], g_h2b[H_S * N_B];
__device__ float g_h3seq[(size_t)(T_S + 1) * H_S * N_B]; // slot s = h3 after step s-1, [k][n]
__device__ float g_R[(size_t)NT * H_S];                // [row][k] row=n*T+t
__device__ float g_W1t[H_S * H_S];                     // [k][j]
__device__ float g_W2t[(size_t)H_S * V_S];             // [k][j]   20.5 MB
__device__ unsigned g_bar[NBAR];                       // grid-barrier counters (zero-init; block 0 resets at end)

// ---------------- helpers ----------------
__device__ __forceinline__ float sigf(float x) { return __fdividef(1.0f, 1.0f + __expf(-x)); }

// packed fp32x2 FMA (Blackwell FFMA2; only reachable via PTX fma.rn.f32x2)
__device__ __forceinline__ void ffma2(unsigned long long& d, unsigned long long a,
                                      unsigned long long b) {
    asm("fma.rn.f32x2 %0, %1, %2, %0;" : "+l"(d) : "l"(a), "l"(b));
}
__device__ __forceinline__ unsigned long long pk2dup(float x) {
    unsigned long long r;
    asm("mov.b64 %0, {%1, %1};" : "=l"(r) : "f"(x));
    return r;
}
__device__ __forceinline__ float2 u2f(unsigned long long v) {
    float2 f;
    asm("mov.b64 {%0, %1}, %2;" : "=f"(f.x), "=f"(f.y) : "l"(v));
    return f;
}
__device__ __forceinline__ unsigned long long f2u(float x, float y) {
    unsigned long long v;
    asm("mov.b64 %0, {%1, %2};" : "=l"(v) : "f"(x), "f"(y));
    return v;
}
// 16-byte L1-bypassing global load (cross-block-produced data must not hit stale L1)
__device__ __forceinline__ float4 ldcg_f4(const float* p) {
    float4 v;
    asm volatile("ld.global.cg.v4.f32 {%0, %1, %2, %3}, [%4];"
                 : "=f"(v.x), "=f"(v.y), "=f"(v.z), "=f"(v.w) : "l"(p));
    return v;
}

// software grid barrier across the 96 co-resident blocks.
// Release: fence + arrive. Acquire: spin until count==RNN_BLOCKS, fence, bar.
// Each counter is used exactly once per run; final barrier is arrive-only (see k_rnn).
__device__ __forceinline__ void gbar(unsigned idx) {
    __threadfence();
    __syncthreads();
    if (threadIdx.x == 0) {
        atomicAdd(&g_bar[idx], 1u);
        while (((volatile unsigned*)g_bar)[idx] < (unsigned)RNN_BLOCKS) { }
        __threadfence();   // acquire side
    }
    __syncthreads();
}

// cooperative stage of one act matrix (256 k x 64 n = 64KB) global -> SMEM.
// Caller guarantees no thread is still READING the buffer. Trailing sync publishes.
__device__ __forceinline__ void stage_acts(float* __restrict__ buf,
                                           const float* __restrict__ src, int tid) {
#pragma unroll
    for (int i = 0; i < (H_S * N_B / 4) / RNN_THREADS; ++i) {   // 16 float4 per thread
        int idx = tid + i * RNN_THREADS;
        *(float4*)(buf + 4 * idx) = ldcg_f4(src + 4 * idx);
    }
    __syncthreads();
}

// ---------------- prep kernels ----------------
__global__ void k_init_state(const float* __restrict__ h0) {
    int i = blockIdx.x * 256 + threadIdx.x;   // grid 64
    if (i >= H_S * N_B) return;
    int k = i / N_B, n = i % N_B;
    float h = h0[n * H_S + k];
    g_h1a[i] = h; g_h2a[i] = h; g_h3seq[i] = h;   // h(-1) parity: t=0 reads the 'a' buffers
}

// tiled transpose: in[rows][cols] -> out[cols][rows]; which: 0 = W1t, 1 = W2t
__global__ void k_transpose(const float* __restrict__ in, int rows, int cols, int which) {
    float* out = which ? g_W2t : g_W1t;
    __shared__ float tile[32][33];
    int c0 = blockIdx.x * 32, r0 = blockIdx.y * 32;
    int tx = threadIdx.x, ty = threadIdx.y;   // 32 x 8
#pragma unroll
    for (int i = 0; i < 32; i += 8) {
        int r = r0 + ty + i, c = c0 + tx;
        if (r < rows && c < cols) tile[ty + i][tx] = in[(size_t)r * cols + c];
    }
    __syncthreads();
#pragma unroll
    for (int i = 0; i < 32; i += 8) {
        int c = c0 + ty + i, r = r0 + tx;
        if (r < rows && c < cols) out[(size_t)c * rows + r] = tile[tx][ty + i];
    }
}

// g1pre[t][j][n] = bih1[j] + bhh1[j] + sum_e emb[x[n,t],e] * Wih1[j,e]
__global__ __launch_bounds__(256) void k_embed(const int* __restrict__ x,
                                               const float* __restrict__ emb,
                                               const float* __restrict__ Wih1,
                                               const float* __restrict__ bih1,
                                               const float* __restrict__ bhh1) {
    __shared__ float es[N_B][E_S + 1];
    __shared__ int xs[N_B];
    const int t = blockIdx.y;
    const int tid = threadIdx.x;
    if (tid < N_B) xs[tid] = x[tid * T_S + t];
    __syncthreads();
    for (int i = tid; i < N_B * E_S; i += 256) {
        int nn = i >> 4, e = i & 15;
        es[nn][e] = emb[(size_t)xs[nn] * E_S + e];
    }
    __syncthreads();
    const int n = tid & 63;
    const int j = blockIdx.x * 4 + (tid >> 6);
    float acc = bih1[j] + bhh1[j];
    const float* w = Wih1 + j * E_S;
#pragma unroll
    for (int e = 0; e < E_S; e++) acc = fmaf(es[n][e], w[e], acc);
    g_g1pre[((size_t)t * G_S + j) * N_B + n] = acc;
}

// ---------------- wavefront-pipelined persistent 3-layer LSTM ----------------
// 96 blocks x 256 threads. group = bid/32 (0->L1, 1->L2, 2->L3); gb = bid%32.
// Warp w (0..7) handles H-row jh = gb*8 + w (all 4 gates). Lane l: n-quad
// q = l&15 (n4 = 4q..4q+3); k-half kh = l>>4; halves combined via shfl+add.f32x2.
//
// Wave schedule (wv = 0..129): L1 computes h1(wv) [wv<128]; L2 computes
// h2(wv-1); L3 computes h3(wv-2). One grid barrier after each wave 0..128.
// RAW: L2@wv reads h1(wv-1) (written wave wv-1) and h2(wv-2) (wave wv-1) —
// both across >=1 barrier. L3@wv reads h2(wv-2) (wave wv-1) and h3seq. ✓
// WAR: h1 parity p written @wv has p=wv&1; L2 reads parity (wv-1)&1 != p. ✓
//      h2 parity (wv-2)&1 read by L3 @wv; next written by L2 @wv+1 (h2(wv),
//      same parity) — separated by gbar(wv). ✓
// Within-block staging-buffer WAR: gbar / explicit __syncthreads between uses.

__device__ __forceinline__ void mat_acc_s(const float* __restrict__ ab,
                                          const unsigned long long* __restrict__ wd,
                                          int kbase, int n4, unsigned long long acc[8]) {
#pragma unroll 4
    for (int k2 = 0; k2 < 64; ++k2) {    // 2 k per iter, 128 k per half-warp
        const int k = kbase + 2 * k2;
        ulonglong2 a0 = *(const ulonglong2*)(ab + (size_t)k * N_B + n4);
        ulonglong2 a1 = *(const ulonglong2*)(ab + (size_t)(k + 1) * N_B + n4);
#pragma unroll
        for (int g = 0; g < 4; ++g) {
            ulonglong2 w2 = *(const ulonglong2*)(wd + g * H_S + k);  // dup(w[k]), dup(w[k+1])
            ffma2(acc[2 * g + 0], w2.x, a0.x);
            ffma2(acc[2 * g + 1], w2.x, a0.y);
            ffma2(acc[2 * g + 0], w2.y, a1.x);
            ffma2(acc[2 * g + 1], w2.y, a1.y);
        }
    }
}

// sum the two k-halves: lane l += lane l+16 (valid in lanes 0-15 afterwards)
__device__ __forceinline__ void combine_halves(unsigned long long acc[8]) {
#pragma unroll
    for (int i = 0; i < 8; ++i) {
        unsigned lo = __shfl_down_sync(0xffffffffu, (unsigned)(acc[i] & 0xffffffffull), 16);
        unsigned hi = __shfl_down_sync(0xffffffffu, (unsigned)(acc[i] >> 32), 16);
        unsigned long long o = ((unsigned long long)hi << 32) | lo;
        asm("add.rn.f32x2 %0, %0, %1;" : "+l"(acc[i]) : "l"(o));
    }
}

// gate nonlinearity + c update + packed 16B h store (lanes 0-15 only)
// acc layout: acc[2*g + p], g: 0=i,1=f,2=g,3=o; p: n-pair half of the quad
__device__ __forceinline__ void cellfin2(const unsigned long long acc[8],
                                         unsigned long long cpk[2],
                                         float* __restrict__ hout, int jh, int n4) {
    float h[4];
#pragma unroll
    for (int p = 0; p < 2; ++p) {
        float2 ai = u2f(acc[0 + p]), af = u2f(acc[2 + p]);
        float2 ag = u2f(acc[4 + p]), ao = u2f(acc[6 + p]);
        float2 c = u2f(cpk[p]);
        float cx = sigf(af.x) * c.x + sigf(ai.x) * tanhf(ag.x);
        float cy = sigf(af.y) * c.y + sigf(ai.y) * tanhf(ag.y);
        cpk[p] = f2u(cx, cy);
        h[2 * p + 0] = sigf(ao.x) * tanhf(cx);
        h[2 * p + 1] = sigf(ao.y) * tanhf(cy);
    }
    asm volatile("st.global.cg.v4.f32 [%0], {%1, %2, %3, %4};"
                 :: "l"(hout + jh * N_B + n4), "f"(h[0]), "f"(h[1]), "f"(h[2]), "f"(h[3])
                 : "memory");
}

__global__ __launch_bounds__(RNN_THREADS, 1) void k_rnn(
    const float* __restrict__ Whh1,
    const float* __restrict__ Wih2, const float* __restrict__ Whh2,
    const float* __restrict__ Wih3, const float* __restrict__ Whh3,
    const float* __restrict__ bih2, const float* __restrict__ bhh2,
    const float* __restrict__ bih3, const float* __restrict__ bhh3,
    const float* __restrict__ c0) {
    extern __shared__ unsigned long long wsd[];   // [<=2 mats][8 warps][4 gates][256 k] dup pairs
    float* ab = (float*)(wsd + WSD_U64);          // act staging buffer [256 k][64 n]
    const int tid   = threadIdx.x;
    const int w     = tid >> 5;          // warp 0..7
    const int lane  = tid & 31;
    const int n4    = (lane & 15) * 4;   // n-quad base
    const int kh    = lane >> 4;         // k-half: 0 or 1
    const int kb    = kh * 128;          // k base for this half
    const int group = blockIdx.x >> 5;   // 0=L1, 1=L2, 2=L3
    const int gb    = blockIdx.x & 31;
    const int jh    = gb * 8 + w;        // H-row for this warp

    // matrices for this group (mat0 = input-act matrix, mat1 = hidden-act matrix)
    const float* m0 = (group == 0) ? Whh1 : (group == 1) ? Wih2 : Wih3;
    const float* m1 = (group == 0) ? (const float*)0 : (group == 1) ? Whh2 : Whh3;
    const int nmats = (group == 0) ? 1 : 2;

    // one-time weight preload, duplicated for f32x2 (coalesced LDG, linear STS)
    for (int idx = tid; idx < nmats * 8 * 4 * H_S; idx += RNN_THREADS) {
        int mat  = idx >> 13;            // 8192 entries per matrix
        int rem  = idx & 8191;
        int ww   = rem >> 10;            // warp row
        int gate = (rem >> 8) & 3;
        int k    = rem & 255;
        const float* src = mat ? m1 : m0;
        float v = __ldg(src + (size_t)(gate * H_S + gb * 8 + ww) * H_S + k);
        wsd[idx] = pk2dup(v);
    }
    // bias sums (packed, duplicated) and register-resident c state (lanes<16)
    unsigned long long bsum[4] = {0ull, 0ull, 0ull, 0ull};
    if (group == 1) {
#pragma unroll
        for (int g = 0; g < 4; ++g)
            bsum[g] = pk2dup(bih2[g * H_S + jh] + bhh2[g * H_S + jh]);
    } else if (group == 2) {
#pragma unroll
        for (int g = 0; g < 4; ++g)
            bsum[g] = pk2dup(bih3[g * H_S + jh] + bhh3[g * H_S + jh]);
    }
    unsigned long long cst[2];
    if (kh == 0) {
        cst[0] = f2u(c0[(n4 + 0) * H_S + jh], c0[(n4 + 1) * H_S + jh]);
        cst[1] = f2u(c0[(n4 + 2) * H_S + jh], c0[(n4 + 3) * H_S + jh]);
    }
    __syncthreads();

    const unsigned long long* wd0 = wsd + ((0 * 8 + w) * 4) * H_S;
    const unsigned long long* wd1 = wsd + ((1 * 8 + w) * 4) * H_S;

    for (int wv = 0; wv < WAVES; ++wv) {
        if (group == 0) {
            // ---- layer 1, t = wv (input part precomputed in g_g1pre) ----
            if (wv < T_S) {
                const int t = wv;
                const float* hin  = (t & 1) ? g_h1b : g_h1a;
                float*       hout = (t & 1) ? g_h1a : g_h1b;
                unsigned long long acc[8];
                if (kh == 0) {
                    const float* pre = g_g1pre + (size_t)t * (G_S * N_B);
#pragma unroll
                    for (int g = 0; g < 4; ++g) {
                        ulonglong2 pv = *(const ulonglong2*)(pre + (size_t)(g * H_S + jh) * N_B + n4);
                        acc[2 * g] = pv.x; acc[2 * g + 1] = pv.y;
                    }
                } else {
#pragma unroll
                    for (int i = 0; i < 8; ++i) acc[i] = 0ull;
                }
                stage_acts(ab, hin, tid);
                mat_acc_s(ab, wd0, kb, n4, acc);
                combine_halves(acc);
                if (kh == 0) cellfin2(acc, cst, hout, jh, n4);
            }
        } else {
            // ---- layer 2 (t = wv-1) or layer 3 (t = wv-2) ----
            const int t = (group == 1) ? wv - 1 : wv - 2;
            if (t >= 0 && t < T_S) {
                const float* xin  = (group == 1)
                    ? ((t & 1) ? g_h1a : g_h1b)                      // h1(t)
                    : ((t & 1) ? g_h2a : g_h2b);                     // h2(t)
                const float* hin  = (group == 1)
                    ? ((t & 1) ? g_h2b : g_h2a)                      // h2(t-1)
                    : (g_h3seq + (size_t)t * (H_S * N_B));           // h3(t-1)
                float*       hout = (group == 1)
                    ? ((t & 1) ? g_h2a : g_h2b)                      // h2(t)
                    : (g_h3seq + (size_t)(t + 1) * (H_S * N_B));     // h3(t)
                unsigned long long acc[8];
#pragma unroll
                for (int g = 0; g < 4; ++g) {
                    acc[2 * g]     = (kh == 0) ? bsum[g] : 0ull;
                    acc[2 * g + 1] = (kh == 0) ? bsum[g] : 0ull;
                }
                stage_acts(ab, xin, tid);
                mat_acc_s(ab, wd0, kb, n4, acc);
                __syncthreads();               // readers done before restage
                stage_acts(ab, hin, tid);
                mat_acc_s(ab, wd1, kb, n4, acc);
                combine_halves(acc);
                if (kh == 0) cellfin2(acc, cst, hout, jh, n4);
            }
        }
        if (wv < WAVES - 1) gbar(wv);          // barriers 0..128
    }

    // ---- final: arrive-only for blocks != 0; block 0 waits then resets all
    // counters. Exiting blocks never read g_bar again -> no reset race. ----
    __threadfence();
    __syncthreads();
    if (blockIdx.x != 0) {
        if (tid == 0) atomicAdd(&g_bar[NBAR - 1], 1u);
        return;
    }
    if (tid == 0) {
        atomicAdd(&g_bar[NBAR - 1], 1u);
        while (((volatile unsigned*)g_bar)[NBAR - 1] < (unsigned)RNN_BLOCKS) { }
        __threadfence();
    }
    __syncthreads();
    for (int i = tid; i < NBAR; i += RNN_THREADS) g_bar[i] = 0;
}

// ---------------- MLP layer 1 (+ReLU), block per timestep ----------------
// R[n*T+t][j] = relu(sum_k h3seq[t+1][k][n] * W1t[k][j] + b1[j])
__global__ __launch_bounds__(256) void k_mlp1(const float* __restrict__ b1) {
    extern __shared__ float hs[];             // [256 k][64 n] = 64KB
    const int t = blockIdx.x;
    const int j = threadIdx.x;
    const float4* src = (const float4*)(g_h3seq + (size_t)(t + 1) * (H_S * N_B));
    float4* hs4 = (float4*)hs;
    for (int i = j; i < H_S * N_B / 4; i += 256) hs4[i] = src[i];
    __syncthreads();
    float bb = b1[j];
#pragma unroll 1
    for (int pass = 0; pass < 4; ++pass) {
        float acc[16];
#pragma unroll
        for (int i = 0; i < 16; ++i) acc[i] = 0.0f;
#pragma unroll 4
        for (int k = 0; k < H_S; ++k) {
            float wv = g_W1t[k * H_S + j];
            const float4* hp = (const float4*)(hs + k * N_B + pass * 16);
            float4 h0 = hp[0], h1 = hp[1], h2 = hp[2], h3 = hp[3];
            acc[0]  = fmaf(h0.x, wv, acc[0]);  acc[1]  = fmaf(h0.y, wv, acc[1]);
            acc[2]  = fmaf(h0.z, wv, acc[2]);  acc[3]  = fmaf(h0.w, wv, acc[3]);
            acc[4]  = fmaf(h1.x, wv, acc[4]);  acc[5]  = fmaf(h1.y, wv, acc[5]);
            acc[6]  = fmaf(h1.z, wv, acc[6]);  acc[7]  = fmaf(h1.w, wv, acc[7]);
            acc[8]  = fmaf(h2.x, wv, acc[8]);  acc[9]  = fmaf(h2.y, wv, acc[9]);
            acc[10] = fmaf(h2.z, wv, acc[10]); acc[11] = fmaf(h2.w, wv, acc[11]);
            acc[12] = fmaf(h3.x, wv, acc[12]); acc[13] = fmaf(h3.y, wv, acc[13]);
            acc[14] = fmaf(h3.z, wv, acc[14]); acc[15] = fmaf(h3.w, wv, acc[15]);
        }
#pragma unroll
        for (int i = 0; i < 16; ++i) {
            int n = pass * 16 + i;
            float v = acc[i] + bb;
            g_R[((size_t)n * T_S + t) * H_S + j] = v > 0.0f ? v : 0.0f;
        }
    }
}

// ---------------- vocab projection: C[8192,20000] = R @ W2t + b2 ----------------
#define BM 128
#define BN 128
#define BK 16
__global__ __launch_bounds__(256, 2) void k_out(const float* __restrict__ b2,
                                                float* __restrict__ C) {
    __shared__ float As[BK][BM];   // [k][m]
    __shared__ float Bs[BK][BN];   // [k][n]
    const int tid = threadIdx.x;
    const int bn = blockIdx.x * BN;
    const int bm = blockIdx.y * BM;
    const int tx = tid & 15, ty = tid >> 4;
    const int m0 = ty * 8, n0 = tx * 8;

    unsigned long long acc[8][4];
#pragma unroll
    for (int i = 0; i < 8; ++i)
#pragma unroll
        for (int j = 0; j < 4; ++j) acc[i][j] = 0ull;

    for (int k0 = 0; k0 < H_S; k0 += BK) {
#pragma unroll
        for (int s = tid; s < (BM * BK) / 4; s += 256) {
            int row = s >> 2, kq = (s & 3) << 2;
            float4 v = *(const float4*)(g_R + (size_t)(bm + row) * H_S + k0 + kq);
            As[kq + 0][row] = v.x; As[kq + 1][row] = v.y;
            As[kq + 2][row] = v.z; As[kq + 3][row] = v.w;
        }
#pragma unroll
        for (int s = tid; s < (BK * BN) / 4; s += 256) {
            int kr = s >> 5, cq = (s & 31) << 2;
            int col = bn + cq;
            float4 v = make_float4(0.f, 0.f, 0.f, 0.f);
            if (col < V_S) v = *(const float4*)(g_W2t + (size_t)(k0 + kr) * V_S + col);
            *(float4*)&Bs[kr][cq] = v;
        }
        __syncthreads();
#pragma unroll
        for (int k = 0; k < BK; ++k) {
            float4 a0 = *(const float4*)&As[k][m0];
            float4 a1 = *(const float4*)&As[k][m0 + 4];
            ulonglong2 bb0 = *(const ulonglong2*)&Bs[k][n0];
            ulonglong2 bb1 = *(const ulonglong2*)&Bs[k][n0 + 4];
            unsigned long long br[4] = { bb0.x, bb0.y, bb1.x, bb1.y };
            float ar[8] = { a0.x, a0.y, a0.z, a0.w, a1.x, a1.y, a1.z, a1.w };
#pragma unroll
            for (int i = 0; i < 8; ++i) {
                unsigned long long ad = pk2dup(ar[i]);
#pragma unroll
                for (int j = 0; j < 4; ++j) ffma2(acc[i][j], ad, br[j]);
            }
        }
        __syncthreads();
    }
#pragma unroll
    for (int i = 0; i < 8; ++i) {
        size_t rowoff = (size_t)(bm + m0 + i) * V_S;
#pragma unroll
        for (int jq = 0; jq < 2; ++jq) {
            int col = bn + n0 + jq * 4;
            if (col < V_S) {
                float4 bias = *(const float4*)(b2 + col);
                float2 p0 = u2f(acc[i][jq * 2]);
                float2 p1 = u2f(acc[i][jq * 2 + 1]);
                float4 o = make_float4(p0.x + bias.x, p0.y + bias.y,
                                       p1.x + bias.z, p1.y + bias.w);
                *(float4*)(C + rowoff + col) = o;
            }
        }
    }
}

// labels (second reference output, cast to output dtype)
__global__ void k_labels(const int* __restrict__ x, float* __restrict__ out, long long out_size) {
    int i = blockIdx.x * 256 + threadIdx.x;
    if (i < NT && NTV + i < out_size) out[NTV + i] = (float)x[i];
}

// ---------------- host launcher ----------------
extern "C" void kernel_launch(void* const* d_in, const int* in_sizes, int n_in,
                              void* d_out, int out_size) {
    const int*   x    = (const int*)d_in[0];
    const float* h0   = (const float*)d_in[1];
    const float* c0   = (const float*)d_in[2];
    const float* emb  = (const float*)d_in[3];
    const float* Wih1 = (const float*)d_in[4];
    const float* Whh1 = (const float*)d_in[5];
    const float* bih1 = (const float*)d_in[6];
    const float* bhh1 = (const float*)d_in[7];
    const float* Wih2 = (const float*)d_in[8];
    const float* Whh2 = (const float*)d_in[9];
    const float* bih2 = (const float*)d_in[10];
    const float* bhh2 = (const float*)d_in[11];
    const float* Wih3 = (const float*)d_in[12];
    const float* Whh3 = (const float*)d_in[13];
    const float* bih3 = (const float*)d_in[14];
    const float* bhh3 = (const float*)d_in[15];
    const float* W1   = (const float*)d_in[16];
    const float* b1   = (const float*)d_in[17];
    const float* W2   = (const float*)d_in[18];
    const float* b2   = (const float*)d_in[19];
    float* out = (float*)d_out;

    cudaFuncSetAttribute(k_rnn,  cudaFuncAttributeMaxDynamicSharedMemorySize, SMEM_RNN);
    cudaFuncSetAttribute(k_mlp1, cudaFuncAttributeMaxDynamicSharedMemorySize, 65536);

    // prep
    k_init_state<<<64, 256>>>(h0);
    k_transpose<<<dim3(8, 8), dim3(32, 8)>>>(W1, H_S, H_S, 0);                 // W1t
    k_transpose<<<dim3(8, (V_S + 31) / 32), dim3(32, 8)>>>(W2, V_S, H_S, 1);   // W2t
    k_embed<<<dim3(G_S / 4, T_S), 256>>>(x, emb, Wih1, bih1, bhh1);

    // wavefront-pipelined persistent recurrence (one launch, 3 layer-groups)
    k_rnn<<<RNN_BLOCKS, RNN_THREADS, SMEM_RNN>>>(Whh1, Wih2, Whh2, Wih3, Whh3,
                                                 bih2, bhh2, bih3, bhh3, c0);

    // batched head
    k_mlp1<<<T_S, 256, 65536>>>(b1);
    k_out<<<dim3((V_S + BN - 1) / BN, NT / BM), 256>>>(b2, out);

    if ((long long)out_size > NTV)
        k_labels<<<(NT + 255) / 256, 256>>>(x, out, (long long)out_size);
}